// round 13
// baseline (speedup 1.0000x reference)
#include <cuda_runtime.h>
#include <math.h>

constexpr int Bb=2, Nseq=2048, Dd=1024, DI=2048, DS=16;
constexpr int Mrows=Bb*Nseq, KTOP=1434, REST=Nseq-KTOP, OUTR=KTOP+1;

__device__ float g_res[Mrows*Dd];
__device__ float g_xn [Mrows*Dd];
__device__ float g_xz [Mrows*2*DI];
__device__ float g_xc [Mrows*DI];
__device__ float g_xdb[Mrows*96];
__device__ float g_dt [Mrows*DI];
__device__ float g_y  [Mrows*DI];
__device__ float g_hs [Mrows*Dd];
__device__ float g_scores[Bb*Nseq];
__device__ unsigned long long g_keys[Bb*Nseq];
__device__ float g_w[Bb*1024];

__device__ __forceinline__ float warp_sum(float v){
#pragma unroll
    for(int o=16;o>0;o>>=1) v+=__shfl_xor_sync(0xffffffffu,v,o);
    return v;
}
__device__ __forceinline__ float warp_max(float v){
#pragma unroll
    for(int o=16;o>0;o>>=1) v=fmaxf(v,__shfl_xor_sync(0xffffffffu,v,o));
    return v;
}
__device__ __forceinline__ float block_sum(float v, float* sh){
    int lane=threadIdx.x&31, wid=threadIdx.x>>5, nw=blockDim.x>>5;
    v=warp_sum(v);
    if(lane==0) sh[wid]=v;
    __syncthreads();
    float t=(threadIdx.x<(unsigned)nw)?sh[threadIdx.x]:0.0f;
    if(wid==0){ t=warp_sum(t); if(lane==0) sh[0]=t; }
    __syncthreads(); float r=sh[0]; __syncthreads(); return r;
}
__device__ __forceinline__ float block_max(float v, float* sh){
    int lane=threadIdx.x&31, wid=threadIdx.x>>5, nw=blockDim.x>>5;
    v=warp_max(v);
    if(lane==0) sh[wid]=v;
    __syncthreads();
    float t=(threadIdx.x<(unsigned)nw)?sh[threadIdx.x]:-__int_as_float(0x7f800000);
    if(wid==0){ t=warp_max(t); if(lane==0) sh[0]=t; }
    __syncthreads(); float r=sh[0]; __syncthreads(); return r;
}
// jax.nn.softplus = logaddexp(x, 0) = max(x,0) + log1p(exp(-|x|))
__device__ __forceinline__ float softplusf_(float x){
    return fmaxf(x,0.0f)+log1pf(expf(-fabsf(x)));
}

// XLA f32 tanh: rational approximation P(x^2)/Q(x^2), strict mul/add rounding.
__device__ __forceinline__ float xla_tanhf(float x){
    if (fabsf(x) < 0.0004f) return x;
    float xc=fminf(fmaxf(x,-7.90531110763549805f),7.90531110763549805f);
    float x2=__fmul_rn(xc,xc);
    float p=-2.76076847742355e-16f;
    p=__fadd_rn(__fmul_rn(x2,p), 2.00018790482477e-13f);
    p=__fadd_rn(__fmul_rn(x2,p),-8.60467152213735e-11f);
    p=__fadd_rn(__fmul_rn(x2,p), 5.12229709037114e-08f);
    p=__fadd_rn(__fmul_rn(x2,p), 1.48572235717979e-05f);
    p=__fadd_rn(__fmul_rn(x2,p), 6.37261928875436e-04f);
    p=__fadd_rn(__fmul_rn(x2,p), 4.89352455891786e-03f);
    float num=__fmul_rn(xc,p);
    float q= 1.19825839466702e-06f;
    q=__fadd_rn(__fmul_rn(x2,q), 1.18534705686654e-04f);
    q=__fadd_rn(__fmul_rn(x2,q), 2.26843463243900e-03f);
    q=__fadd_rn(__fmul_rn(x2,q), 4.89352518554385e-03f);
    return __fdiv_rn(num,q);
}
// XLA silu: x * (0.5 + 0.5*tanh(0.5*x))
__device__ __forceinline__ float silu_xla(float x){
    float t=xla_tanhf(__fmul_rn(0.5f,x));
    float sg=__fadd_rn(0.5f,__fmul_rn(0.5f,t));
    return __fmul_rn(x,sg);
}

// shfl_down 5-level tree, strict rounding (XLA EmitFullWarpShuffleDownLoop)
__device__ __forceinline__ float tree_reduce_warp(float p){
#pragma unroll
    for(int off=16;off>0;off>>=1)
        p=__fadd_rn(p,__shfl_down_sync(0xffffffffu,p,off));
    return p;
}

// 1) add + rmsnorm. XLA:GPU f32 row-reduce, 1024 threads x vec1 (R12 config).
__global__ void add_rmsnorm_kernel(const float* __restrict__ hs, const float* __restrict__ res,
                                   const float* __restrict__ w){
    __shared__ float sw[32];
    __shared__ float s_inv;
    int row=blockIdx.x, t=threadIdx.x;        // 1024 threads
    int lane=t&31, wid=t>>5;
    size_t base=(size_t)row*Dd+t;
    float v=__fadd_rn(hs[base],res[base]);
    g_res[base]=v;
    float p=__fmul_rn(v,v);
    p=tree_reduce_warp(p);
    if(lane==0) sw[wid]=p;
    __syncthreads();
    if(wid==0){
        float q=sw[lane];
        q=tree_reduce_warp(q);
        if(lane==0){
            float m=__fadd_rn(__fmul_rn(q,(1.0f/1024.0f)),1e-5f);
            s_inv=rsqrtf(m);
        }
    }
    __syncthreads();
    float inv=s_inv;
    g_xn[base]=__fmul_rn(__fmul_rn(v,inv),w[t]);
}

// CR GEMM: fp64 accumulation, single fp32 rounding at the end.
// C[M,Nc]=A[M,K](lda)@Bw[Nc,K]^T. 64x64 tile, 16-k stage, 4x4 per thread.
// Element results are correctly rounded (realization-independent).
__launch_bounds__(256,2)
__global__ void cgemm_kernel(const float* __restrict__ A, const float* __restrict__ Bw,
                             float* __restrict__ C, int Nc, int K, int lda){
    __shared__ __align__(16) float As[16][64];
    __shared__ __align__(16) float Bs[16][64];
    int tid=threadIdx.x, bx=blockIdx.x, by=blockIdx.y;
    int arow=tid>>2, ac4=(tid&3)<<2;
    const float* Ap=A+(size_t)(by*64+arow)*lda+ac4;
    const float* Bp=Bw+(size_t)(bx*64+arow)*K+ac4;
    int tx=tid&15, ty=tid>>4;
    double acc[4][4];
#pragma unroll
    for(int i=0;i<4;i++)
#pragma unroll
        for(int j=0;j<4;j++) acc[i][j]=0.0;
    for(int k0=0;k0<K;k0+=16){
        float4 av=*(const float4*)Ap; Ap+=16;
        float4 bv=*(const float4*)Bp; Bp+=16;
        As[ac4+0][arow]=av.x; As[ac4+1][arow]=av.y;
        As[ac4+2][arow]=av.z; As[ac4+3][arow]=av.w;
        Bs[ac4+0][arow]=bv.x; Bs[ac4+1][arow]=bv.y;
        Bs[ac4+2][arow]=bv.z; Bs[ac4+3][arow]=bv.w;
        __syncthreads();
#pragma unroll
        for(int kk=0;kk<16;kk++){
            double ar_[4], br_[4];
#pragma unroll
            for(int i=0;i<4;i++) ar_[i]=(double)As[kk][ty*4+i];
#pragma unroll
            for(int j=0;j<4;j++) br_[j]=(double)Bs[kk][tx*4+j];
#pragma unroll
            for(int i=0;i<4;i++)
#pragma unroll
                for(int j=0;j<4;j++) acc[i][j]=fma(ar_[i],br_[j],acc[i][j]);
        }
        __syncthreads();
    }
#pragma unroll
    for(int i=0;i<4;i++){
        int row=by*64+ty*4+i;
        int col=bx*64+tx*4;
        float4 o;
        o.x=(float)acc[i][0]; o.y=(float)acc[i][1];
        o.z=(float)acc[i][2]; o.w=(float)acc[i][3];
        *(float4*)(C+(size_t)row*Nc+col)=o;
    }
}

// Kahan GEMM (x_proj/dt; non-critical path). EPI 0: none. EPI 1: softplus(acc+bias).
template <int EPI>
__launch_bounds__(256,1)
__global__ void kgemm_kernel(const float* __restrict__ A, const float* __restrict__ Bw,
                             float* __restrict__ C, const float* __restrict__ bias,
                             int Nc, int K, int lda){
    __shared__ __align__(16) float As[8][128];
    __shared__ __align__(16) float Bs[8][64];
    int tid=threadIdx.x, bx=blockIdx.x, by=blockIdx.y;
    int arow=tid>>1, ak4=(tid&1)<<2;
    const float* Ap=A+(size_t)(by*128+arow)*lda+ak4;
    int brow=(tid<128)?(tid>>1):0;
    int nrow=bx*64+brow;
    if(nrow>=Nc) nrow=Nc-1;
    const float* Bp=Bw+(size_t)nrow*K+ak4;
    int tx=tid&15, ty=tid>>4;
    float acc[8][4], car[8][4];
#pragma unroll
    for(int i=0;i<8;i++)
#pragma unroll
        for(int j=0;j<4;j++){ acc[i][j]=0.f; car[i][j]=0.f; }
    for(int k0=0;k0<K;k0+=8){
        float4 av=*(const float4*)Ap; Ap+=8;
        float4 bv=make_float4(0.f,0.f,0.f,0.f);
        if(tid<128) bv=*(const float4*)Bp;
        Bp+=8;
        As[ak4+0][arow]=av.x; As[ak4+1][arow]=av.y;
        As[ak4+2][arow]=av.z; As[ak4+3][arow]=av.w;
        if(tid<128){
            Bs[ak4+0][brow]=bv.x; Bs[ak4+1][brow]=bv.y;
            Bs[ak4+2][brow]=bv.z; Bs[ak4+3][brow]=bv.w;
        }
        __syncthreads();
        float pt[8][4];
#pragma unroll
        for(int i=0;i<8;i++)
#pragma unroll
            for(int j=0;j<4;j++) pt[i][j]=0.f;
#pragma unroll
        for(int kk=0;kk<8;kk++){
            float ar_[8], br_[4];
            *(float4*)(ar_)=*(const float4*)&As[kk][ty*8];
            *(float4*)(ar_+4)=*(const float4*)&As[kk][ty*8+4];
            *(float4*)(br_)=*(const float4*)&Bs[kk][tx*4];
#pragma unroll
            for(int i=0;i<8;i++)
#pragma unroll
                for(int j=0;j<4;j++) pt[i][j]=fmaf(ar_[i],br_[j],pt[i][j]);
        }
#pragma unroll
        for(int i=0;i<8;i++)
#pragma unroll
            for(int j=0;j<4;j++){
                float y=pt[i][j]-car[i][j];
                float t=acc[i][j]+y;
                car[i][j]=(t-acc[i][j])-y;
                acc[i][j]=t;
            }
        __syncthreads();
    }
#pragma unroll
    for(int i=0;i<8;i++){
        int row=by*128+ty*8+i, col=bx*64+tx*4;
        if(col+3<Nc){
            float4 o;
            if(EPI==1){
                o.x=softplusf_(__fadd_rn(acc[i][0]+car[i][0],bias[col+0]));
                o.y=softplusf_(__fadd_rn(acc[i][1]+car[i][1],bias[col+1]));
                o.z=softplusf_(__fadd_rn(acc[i][2]+car[i][2],bias[col+2]));
                o.w=softplusf_(__fadd_rn(acc[i][3]+car[i][3],bias[col+3]));
            } else {
                o.x=acc[i][0]+car[i][0]; o.y=acc[i][1]+car[i][1];
                o.z=acc[i][2]+car[i][2]; o.w=acc[i][3]+car[i][3];
            }
            *(float4*)(C+(size_t)row*Nc+col)=o;
        }
    }
}

// conv + XLA silu (strict mul/add rounding)
__global__ void conv_silu_kernel(const float* __restrict__ cw, const float* __restrict__ cb){
    int idx=blockIdx.x*blockDim.x+threadIdx.x;
    if(idx>=Mrows*DI) return;
    int row=idx>>11, c=idx&(DI-1), n=row&(Nseq-1);
    float w0=cw[c*4+0], w1=cw[c*4+1], w2=cw[c*4+2], w3=cw[c*4+3];
    const float* xp=g_xz+(size_t)row*(2*DI)+c;
    float acc=0.0f;
    if(n>=3) acc=__fadd_rn(acc,__fmul_rn(xp[-3*(2*DI)],w0));
    if(n>=2) acc=__fadd_rn(acc,__fmul_rn(xp[-2*(2*DI)],w1));
    if(n>=1) acc=__fadd_rn(acc,__fmul_rn(xp[-1*(2*DI)],w2));
    acc=__fadd_rn(acc,__fmul_rn(xp[0],w3));
    acc=__fadd_rn(acc,cb[c]);
    g_xc[idx]=silu_xla(acc);
}

// scan: 1 thread per channel, 16 states in registers, strict per-op rounding.
__global__ void scan_kernel(const float* __restrict__ A_log, const float* __restrict__ D_param){
    int g=blockIdx.x*128+threadIdx.x;
    int b=g>>11, d=g&(DI-1);
    float a[DS], h[DS];
#pragma unroll
    for(int s=0;s<DS;s++){ a[s]=-expf(A_log[d*DS+s]); h[s]=0.0f; }
    float Dp=D_param[d];
    const float* dtp=g_dt+(size_t)(b*Nseq)*DI+d;
    const float* xcp=g_xc+(size_t)(b*Nseq)*DI+d;
    const float* zp =g_xz+(size_t)(b*Nseq)*(2*DI)+DI+d;
    const float* bcp=g_xdb+(size_t)(b*Nseq)*96+64;
    float* yp=g_y+(size_t)(b*Nseq)*DI+d;
    for(int n=0;n<Nseq;n++){
        float dtv=__ldg(dtp), xv=__ldg(xcp), zv=__ldg(zp);
        float dtx=__fmul_rn(dtv,xv);
        float y=0.0f;
#pragma unroll
        for(int s=0;s<DS;s++){
            float Bv=__ldg(bcp+s), Cv=__ldg(bcp+16+s);
            float dA=expf(__fmul_rn(dtv,a[s]));
            h[s]=__fadd_rn(__fmul_rn(dA,h[s]),__fmul_rn(dtx,Bv));
            y=__fadd_rn(y,__fmul_rn(h[s],Cv));
        }
        float y2=__fadd_rn(y,__fmul_rn(Dp,xv));
        yp[0]=__fmul_rn(y2,silu_xla(zv));
        dtp+=DI; xcp+=DI; zp+=2*DI; bcp+=96; yp+=DI;
    }
}

// scores: XLA 1024-thread vec1 structural reduce on relu(hs) (R12 config)
__global__ void scores_kernel(){
    __shared__ float sw[32];
    int row=blockIdx.x, t=threadIdx.x;        // 1024 threads
    int lane=t&31, wid=t>>5;
    float p=fmaxf(g_hs[(size_t)row*Dd+t],0.0f);
    p=tree_reduce_warp(p);
    if(lane==0) sw[wid]=p;
    __syncthreads();
    if(wid==0){
        float q=sw[lane];
        q=tree_reduce_warp(q);
        if(lane==0)
            g_scores[row]=(q==0.0f)?__int_as_float(0xff800000):q;
    }
}

__global__ void sort_kernel(){
    __shared__ unsigned long long sk[2048];
    int b=blockIdx.x, tid=threadIdx.x;
    for(int i=tid;i<2048;i+=1024){
        float s=g_scores[b*Nseq+i];
        unsigned u=__float_as_uint(s);
        unsigned ord=(u&0x80000000u)?~u:(u|0x80000000u);
        sk[i]=((unsigned long long)(~ord)<<32)|(unsigned)i;
    }
    __syncthreads();
    for(int k=2;k<=2048;k<<=1){
        for(int j=k>>1;j>0;j>>=1){
            for(int i=tid;i<2048;i+=1024){
                int ixj=i^j;
                if(ixj>i){
                    bool up=((i&k)==0);
                    unsigned long long x=sk[i], y=sk[ixj];
                    if((x>y)==up){ sk[i]=y; sk[ixj]=x; }
                }
            }
            __syncthreads();
        }
    }
    for(int i=tid;i<2048;i+=1024) g_keys[b*Nseq+i]=sk[i];
}

__global__ void softmax_rest_kernel(){
    __shared__ float sh[32];
    int b=blockIdx.x, tid=threadIdx.x;
    bool valid=tid<REST;
    float s=-__int_as_float(0x7f800000);
    if(valid){
        int idx=(int)(g_keys[b*Nseq+KTOP+tid]&0xffffffffu);
        s=g_scores[b*Nseq+idx];
    }
    float m=block_max(s,sh);
    float e=valid?expf(s-m):0.0f;
    float sum=block_sum(e,sh);
    g_w[b*1024+tid]=valid?(e/sum):0.0f;
}

__global__ void gather_kernel(float* __restrict__ out){
    int t=blockIdx.x*blockDim.x+threadIdx.x;
    if(t>=Bb*KTOP*256) return;
    int c4=t&255, r=t>>8, b=r/KTOP, i=r-b*KTOP;
    int idx=(int)(g_keys[b*Nseq+i]&0xffffffffu);
    size_t src=((size_t)(b*Nseq+idx))*1024+c4*4;
    size_t dst=((size_t)(b*OUTR+i))*1024+c4*4;
    *(float4*)(out+dst)=*(const float4*)(g_hs+src);
    *(float4*)(out+(size_t)Bb*OUTR*1024+dst)=*(const float4*)(g_res+src);
}

__global__ void fused_kernel(float* __restrict__ out){
    int b=blockIdx.x>>3, chunk=blockIdx.x&7;
    int col=chunk*128+threadIdx.x;
    float ah=0.f, ar=0.f;
    for(int i=0;i<REST;i++){
        int idx=(int)(g_keys[b*Nseq+KTOP+i]&0xffffffffu);
        float w=g_w[b*1024+i];
        size_t base=((size_t)(b*Nseq+idx))*1024+col;
        ah=fmaf(w,g_hs[base],ah);
        ar=fmaf(w,g_res[base],ar);
    }
    size_t dst=((size_t)(b*OUTR+KTOP))*1024+col;
    out[dst]=ah;
    out[(size_t)Bb*OUTR*1024+dst]=ar;
}

extern "C" void kernel_launch(void* const* d_in, const int* in_sizes, int n_in,
                              void* d_out, int out_size){
    const float* hidden=(const float*)d_in[0];
    const float* residual=(const float*)d_in[1];
    const float* norm_w=(const float*)d_in[2];
    const float* in_proj_w=(const float*)d_in[3];
    const float* conv_w=(const float*)d_in[4];
    const float* conv_b=(const float*)d_in[5];
    const float* x_proj_w=(const float*)d_in[6];
    const float* dt_proj_w=(const float*)d_in[7];
    const float* dt_proj_b=(const float*)d_in[8];
    const float* A_log=(const float*)d_in[9];
    const float* D_param=(const float*)d_in[10];
    const float* out_proj_w=(const float*)d_in[11];
    float* out=(float*)d_out;

    float *p_xn,*p_xz,*p_xc,*p_xdb,*p_dt,*p_y,*p_hs;
    cudaGetSymbolAddress((void**)&p_xn,g_xn);
    cudaGetSymbolAddress((void**)&p_xz,g_xz);
    cudaGetSymbolAddress((void**)&p_xc,g_xc);
    cudaGetSymbolAddress((void**)&p_xdb,g_xdb);
    cudaGetSymbolAddress((void**)&p_dt,g_dt);
    cudaGetSymbolAddress((void**)&p_y,g_y);
    cudaGetSymbolAddress((void**)&p_hs,g_hs);

    add_rmsnorm_kernel<<<Mrows,1024>>>(hidden,residual,norm_w);
    // in_proj: [4096 x 4096], K=1024  (CR / fp64 accumulation)
    cgemm_kernel<<<dim3(64,64),256>>>(p_xn,in_proj_w,p_xz,2*DI,Dd,Dd);
    conv_silu_kernel<<<(Mrows*DI)/256,256>>>(conv_w,conv_b);
    // x_proj: [4096 x 96], K=2048  (Kahan)
    kgemm_kernel<0><<<dim3(2,32),256>>>(p_xc,x_proj_w,p_xdb,nullptr,96,DI,DI);
    // dt: softplus([4096 x 2048] @ dtw^T + b), K=64, lda=96  (Kahan)
    kgemm_kernel<1><<<dim3(32,32),256>>>(p_xdb,dt_proj_w,p_dt,dt_proj_b,DI,64,96);
    scan_kernel<<<32,128>>>(A_log,D_param);
    // out_proj: [4096 x 1024], K=2048  (CR / fp64 accumulation)
    cgemm_kernel<<<dim3(16,64),256>>>(p_y,out_proj_w,p_hs,Dd,DI,DI);
    scores_kernel<<<Mrows,1024>>>();
    sort_kernel<<<Bb,1024>>>();
    softmax_rest_kernel<<<Bb,1024>>>();
    gather_kernel<<<(Bb*KTOP*256+255)/256,256>>>(out);
    fused_kernel<<<Bb*8,128>>>(out);
}

// round 14
// speedup vs baseline: 7.1601x; 7.1601x over previous
#include <cuda_runtime.h>
#include <math.h>

constexpr int Bb=2, Nseq=2048, Dd=1024, DI=2048, DS=16;
constexpr int Mrows=Bb*Nseq, KTOP=1434, REST=Nseq-KTOP, OUTR=KTOP+1;

__device__ float g_res[Mrows*Dd];
__device__ float g_xn [Mrows*Dd];
__device__ float g_xz [Mrows*2*DI];
__device__ float g_xc [Mrows*DI];
__device__ float g_xdb[Mrows*96];
__device__ float g_dt [Mrows*DI];
__device__ float g_y  [Mrows*DI];
__device__ float g_hs [Mrows*Dd];
__device__ float g_scores[Bb*Nseq];
__device__ unsigned long long g_keys[Bb*Nseq];
__device__ float g_w[Bb*1024];

__device__ __forceinline__ float warp_sum(float v){
#pragma unroll
    for(int o=16;o>0;o>>=1) v+=__shfl_xor_sync(0xffffffffu,v,o);
    return v;
}
__device__ __forceinline__ float warp_max(float v){
#pragma unroll
    for(int o=16;o>0;o>>=1) v=fmaxf(v,__shfl_xor_sync(0xffffffffu,v,o));
    return v;
}
__device__ __forceinline__ float block_sum(float v, float* sh){
    int lane=threadIdx.x&31, wid=threadIdx.x>>5, nw=blockDim.x>>5;
    v=warp_sum(v);
    if(lane==0) sh[wid]=v;
    __syncthreads();
    float t=(threadIdx.x<(unsigned)nw)?sh[threadIdx.x]:0.0f;
    if(wid==0){ t=warp_sum(t); if(lane==0) sh[0]=t; }
    __syncthreads(); float r=sh[0]; __syncthreads(); return r;
}
__device__ __forceinline__ float block_max(float v, float* sh){
    int lane=threadIdx.x&31, wid=threadIdx.x>>5, nw=blockDim.x>>5;
    v=warp_max(v);
    if(lane==0) sh[wid]=v;
    __syncthreads();
    float t=(threadIdx.x<(unsigned)nw)?sh[threadIdx.x]:-__int_as_float(0x7f800000);
    if(wid==0){ t=warp_max(t); if(lane==0) sh[0]=t; }
    __syncthreads(); float r=sh[0]; __syncthreads(); return r;
}
// jax.nn.softplus = logaddexp(x, 0) = max(x,0) + log1p(exp(-|x|))
__device__ __forceinline__ float softplusf_(float x){
    return fmaxf(x,0.0f)+log1pf(expf(-fabsf(x)));
}

// XLA f32 tanh: rational approximation P(x^2)/Q(x^2), strict mul/add rounding.
__device__ __forceinline__ float xla_tanhf(float x){
    if (fabsf(x) < 0.0004f) return x;
    float xc=fminf(fmaxf(x,-7.90531110763549805f),7.90531110763549805f);
    float x2=__fmul_rn(xc,xc);
    float p=-2.76076847742355e-16f;
    p=__fadd_rn(__fmul_rn(x2,p), 2.00018790482477e-13f);
    p=__fadd_rn(__fmul_rn(x2,p),-8.60467152213735e-11f);
    p=__fadd_rn(__fmul_rn(x2,p), 5.12229709037114e-08f);
    p=__fadd_rn(__fmul_rn(x2,p), 1.48572235717979e-05f);
    p=__fadd_rn(__fmul_rn(x2,p), 6.37261928875436e-04f);
    p=__fadd_rn(__fmul_rn(x2,p), 4.89352455891786e-03f);
    float num=__fmul_rn(xc,p);
    float q= 1.19825839466702e-06f;
    q=__fadd_rn(__fmul_rn(x2,q), 1.18534705686654e-04f);
    q=__fadd_rn(__fmul_rn(x2,q), 2.26843463243900e-03f);
    q=__fadd_rn(__fmul_rn(x2,q), 4.89352518554385e-03f);
    return __fdiv_rn(num,q);
}
// XLA silu: x * (0.5 + 0.5*tanh(0.5*x))
__device__ __forceinline__ float silu_xla(float x){
    float t=xla_tanhf(__fmul_rn(0.5f,x));
    float sg=__fadd_rn(0.5f,__fmul_rn(0.5f,t));
    return __fmul_rn(x,sg);
}

// shfl_down 5-level tree, strict rounding
__device__ __forceinline__ float tree_reduce_warp(float p){
#pragma unroll
    for(int off=16;off>0;off>>=1)
        p=__fadd_rn(p,__shfl_down_sync(0xffffffffu,p,off));
    return p;
}

// 1) add + rmsnorm. XLA:GPU f32 row-reduce, 1024 threads x vec1 (R13 config).
__global__ void add_rmsnorm_kernel(const float* __restrict__ hs, const float* __restrict__ res,
                                   const float* __restrict__ w){
    __shared__ float sw[32];
    __shared__ float s_inv;
    int row=blockIdx.x, t=threadIdx.x;        // 1024 threads
    int lane=t&31, wid=t>>5;
    size_t base=(size_t)row*Dd+t;
    float v=__fadd_rn(hs[base],res[base]);
    g_res[base]=v;
    float p=__fmul_rn(v,v);
    p=tree_reduce_warp(p);
    if(lane==0) sw[wid]=p;
    __syncthreads();
    if(wid==0){
        float q=sw[lane];
        q=tree_reduce_warp(q);
        if(lane==0){
            float m=__fadd_rn(__fmul_rn(q,(1.0f/1024.0f)),1e-5f);
            s_inv=rsqrtf(m);
        }
    }
    __syncthreads();
    float inv=s_inv;
    g_xn[base]=__fmul_rn(__fmul_rn(v,inv),w[t]);
}

// dot2k GEMM: near-correctly-rounded fp32 elements via exact 2Prod (FMA error
// extraction) + per-MAC Kahan accumulation + plain error-term sum.
// Total element error O(eps^2 * sum|p|) -- matches fp64-CR bits except ~1e-5
// of elements by 1 ulp. 128x64 tile, 8x4 micro. C[M,Nc]=A[M,K](lda)@Bw[Nc,K]^T.
__launch_bounds__(256,1)
__global__ void dgemm_kernel(const float* __restrict__ A, const float* __restrict__ Bw,
                             float* __restrict__ C, int Nc, int K, int lda){
    __shared__ __align__(16) float As[8][128];
    __shared__ __align__(16) float Bs[8][64];
    int tid=threadIdx.x, bx=blockIdx.x, by=blockIdx.y;
    int arow=tid>>1, ak4=(tid&1)<<2;
    const float* Ap=A+(size_t)(by*128+arow)*lda+ak4;
    int brow=(tid<128)?(tid>>1):0;
    const float* Bp=Bw+(size_t)(bx*64+brow)*K+ak4;
    int tx=tid&15, ty=tid>>4;
    float acc[8][4], cmp[8][4], esum[8][4];
#pragma unroll
    for(int i=0;i<8;i++)
#pragma unroll
        for(int j=0;j<4;j++){ acc[i][j]=0.f; cmp[i][j]=0.f; esum[i][j]=0.f; }
    for(int k0=0;k0<K;k0+=8){
        float4 av=*(const float4*)Ap; Ap+=8;
        float4 bv=make_float4(0.f,0.f,0.f,0.f);
        if(tid<128) bv=*(const float4*)Bp;
        Bp+=8;
        As[ak4+0][arow]=av.x; As[ak4+1][arow]=av.y;
        As[ak4+2][arow]=av.z; As[ak4+3][arow]=av.w;
        if(tid<128){
            Bs[ak4+0][brow]=bv.x; Bs[ak4+1][brow]=bv.y;
            Bs[ak4+2][brow]=bv.z; Bs[ak4+3][brow]=bv.w;
        }
        __syncthreads();
#pragma unroll
        for(int kk=0;kk<8;kk++){
            float ar_[8], br_[4];
            *(float4*)(ar_)=*(const float4*)&As[kk][ty*8];
            *(float4*)(ar_+4)=*(const float4*)&As[kk][ty*8+4];
            *(float4*)(br_)=*(const float4*)&Bs[kk][tx*4];
#pragma unroll
            for(int i=0;i<8;i++)
#pragma unroll
                for(int j=0;j<4;j++){
                    float p=__fmul_rn(ar_[i],br_[j]);
                    float e=__fmaf_rn(ar_[i],br_[j],-p);   // exact product error
                    float y=p-cmp[i][j];                    // Kahan add of p
                    float t=acc[i][j]+y;
                    cmp[i][j]=(t-acc[i][j])-y;
                    acc[i][j]=t;
                    esum[i][j]+=e;
                }
        }
        __syncthreads();
    }
#pragma unroll
    for(int i=0;i<8;i++){
        int row=by*128+ty*8+i, col=bx*64+tx*4;
        float4 o;
        o.x=acc[i][0]+(esum[i][0]-cmp[i][0]);
        o.y=acc[i][1]+(esum[i][1]-cmp[i][1]);
        o.z=acc[i][2]+(esum[i][2]-cmp[i][2]);
        o.w=acc[i][3]+(esum[i][3]-cmp[i][3]);
        *(float4*)(C+(size_t)row*Nc+col)=o;
    }
}

// Kahan GEMM (x_proj/dt; non-critical path). EPI 0: none. EPI 1: softplus(acc+bias).
template <int EPI>
__launch_bounds__(256,1)
__global__ void kgemm_kernel(const float* __restrict__ A, const float* __restrict__ Bw,
                             float* __restrict__ C, const float* __restrict__ bias,
                             int Nc, int K, int lda){
    __shared__ __align__(16) float As[8][128];
    __shared__ __align__(16) float Bs[8][64];
    int tid=threadIdx.x, bx=blockIdx.x, by=blockIdx.y;
    int arow=tid>>1, ak4=(tid&1)<<2;
    const float* Ap=A+(size_t)(by*128+arow)*lda+ak4;
    int brow=(tid<128)?(tid>>1):0;
    int nrow=bx*64+brow;
    if(nrow>=Nc) nrow=Nc-1;
    const float* Bp=Bw+(size_t)nrow*K+ak4;
    int tx=tid&15, ty=tid>>4;
    float acc[8][4], car[8][4];
#pragma unroll
    for(int i=0;i<8;i++)
#pragma unroll
        for(int j=0;j<4;j++){ acc[i][j]=0.f; car[i][j]=0.f; }
    for(int k0=0;k0<K;k0+=8){
        float4 av=*(const float4*)Ap; Ap+=8;
        float4 bv=make_float4(0.f,0.f,0.f,0.f);
        if(tid<128) bv=*(const float4*)Bp;
        Bp+=8;
        As[ak4+0][arow]=av.x; As[ak4+1][arow]=av.y;
        As[ak4+2][arow]=av.z; As[ak4+3][arow]=av.w;
        if(tid<128){
            Bs[ak4+0][brow]=bv.x; Bs[ak4+1][brow]=bv.y;
            Bs[ak4+2][brow]=bv.z; Bs[ak4+3][brow]=bv.w;
        }
        __syncthreads();
        float pt[8][4];
#pragma unroll
        for(int i=0;i<8;i++)
#pragma unroll
            for(int j=0;j<4;j++) pt[i][j]=0.f;
#pragma unroll
        for(int kk=0;kk<8;kk++){
            float ar_[8], br_[4];
            *(float4*)(ar_)=*(const float4*)&As[kk][ty*8];
            *(float4*)(ar_+4)=*(const float4*)&As[kk][ty*8+4];
            *(float4*)(br_)=*(const float4*)&Bs[kk][tx*4];
#pragma unroll
            for(int i=0;i<8;i++)
#pragma unroll
                for(int j=0;j<4;j++) pt[i][j]=fmaf(ar_[i],br_[j],pt[i][j]);
        }
#pragma unroll
        for(int i=0;i<8;i++)
#pragma unroll
            for(int j=0;j<4;j++){
                float y=pt[i][j]-car[i][j];
                float t=acc[i][j]+y;
                car[i][j]=(t-acc[i][j])-y;
                acc[i][j]=t;
            }
        __syncthreads();
    }
#pragma unroll
    for(int i=0;i<8;i++){
        int row=by*128+ty*8+i, col=bx*64+tx*4;
        if(col+3<Nc){
            float4 o;
            if(EPI==1){
                o.x=softplusf_(__fadd_rn(acc[i][0]+car[i][0],bias[col+0]));
                o.y=softplusf_(__fadd_rn(acc[i][1]+car[i][1],bias[col+1]));
                o.z=softplusf_(__fadd_rn(acc[i][2]+car[i][2],bias[col+2]));
                o.w=softplusf_(__fadd_rn(acc[i][3]+car[i][3],bias[col+3]));
            } else {
                o.x=acc[i][0]+car[i][0]; o.y=acc[i][1]+car[i][1];
                o.z=acc[i][2]+car[i][2]; o.w=acc[i][3]+car[i][3];
            }
            *(float4*)(C+(size_t)row*Nc+col)=o;
        }
    }
}

// conv + XLA silu (strict mul/add rounding)
__global__ void conv_silu_kernel(const float* __restrict__ cw, const float* __restrict__ cb){
    int idx=blockIdx.x*blockDim.x+threadIdx.x;
    if(idx>=Mrows*DI) return;
    int row=idx>>11, c=idx&(DI-1), n=row&(Nseq-1);
    float w0=cw[c*4+0], w1=cw[c*4+1], w2=cw[c*4+2], w3=cw[c*4+3];
    const float* xp=g_xz+(size_t)row*(2*DI)+c;
    float acc=0.0f;
    if(n>=3) acc=__fadd_rn(acc,__fmul_rn(xp[-3*(2*DI)],w0));
    if(n>=2) acc=__fadd_rn(acc,__fmul_rn(xp[-2*(2*DI)],w1));
    if(n>=1) acc=__fadd_rn(acc,__fmul_rn(xp[-1*(2*DI)],w2));
    acc=__fadd_rn(acc,__fmul_rn(xp[0],w3));
    acc=__fadd_rn(acc,cb[c]);
    g_xc[idx]=silu_xla(acc);
}

// scan: 1 thread per channel, 16 states in registers, strict per-op rounding.
__global__ void scan_kernel(const float* __restrict__ A_log, const float* __restrict__ D_param){
    int g=blockIdx.x*128+threadIdx.x;
    int b=g>>11, d=g&(DI-1);
    float a[DS], h[DS];
#pragma unroll
    for(int s=0;s<DS;s++){ a[s]=-expf(A_log[d*DS+s]); h[s]=0.0f; }
    float Dp=D_param[d];
    const float* dtp=g_dt+(size_t)(b*Nseq)*DI+d;
    const float* xcp=g_xc+(size_t)(b*Nseq)*DI+d;
    const float* zp =g_xz+(size_t)(b*Nseq)*(2*DI)+DI+d;
    const float* bcp=g_xdb+(size_t)(b*Nseq)*96+64;
    float* yp=g_y+(size_t)(b*Nseq)*DI+d;
    for(int n=0;n<Nseq;n++){
        float dtv=__ldg(dtp), xv=__ldg(xcp), zv=__ldg(zp);
        float dtx=__fmul_rn(dtv,xv);
        float y=0.0f;
#pragma unroll
        for(int s=0;s<DS;s++){
            float Bv=__ldg(bcp+s), Cv=__ldg(bcp+16+s);
            float dA=expf(__fmul_rn(dtv,a[s]));
            h[s]=__fadd_rn(__fmul_rn(dA,h[s]),__fmul_rn(dtx,Bv));
            y=__fadd_rn(y,__fmul_rn(h[s],Cv));
        }
        float y2=__fadd_rn(y,__fmul_rn(Dp,xv));
        yp[0]=__fmul_rn(y2,silu_xla(zv));
        dtp+=DI; xcp+=DI; zp+=2*DI; bcp+=96; yp+=DI;
    }
}

// scores: XLA 1024-thread vec1 structural reduce on relu(hs) (R13 config)
__global__ void scores_kernel(){
    __shared__ float sw[32];
    int row=blockIdx.x, t=threadIdx.x;        // 1024 threads
    int lane=t&31, wid=t>>5;
    float p=fmaxf(g_hs[(size_t)row*Dd+t],0.0f);
    p=tree_reduce_warp(p);
    if(lane==0) sw[wid]=p;
    __syncthreads();
    if(wid==0){
        float q=sw[lane];
        q=tree_reduce_warp(q);
        if(lane==0)
            g_scores[row]=(q==0.0f)?__int_as_float(0xff800000):q;
    }
}

__global__ void sort_kernel(){
    __shared__ unsigned long long sk[2048];
    int b=blockIdx.x, tid=threadIdx.x;
    for(int i=tid;i<2048;i+=1024){
        float s=g_scores[b*Nseq+i];
        unsigned u=__float_as_uint(s);
        unsigned ord=(u&0x80000000u)?~u:(u|0x80000000u);
        sk[i]=((unsigned long long)(~ord)<<32)|(unsigned)i;
    }
    __syncthreads();
    for(int k=2;k<=2048;k<<=1){
        for(int j=k>>1;j>0;j>>=1){
            for(int i=tid;i<2048;i+=1024){
                int ixj=i^j;
                if(ixj>i){
                    bool up=((i&k)==0);
                    unsigned long long x=sk[i], y=sk[ixj];
                    if((x>y)==up){ sk[i]=y; sk[ixj]=x; }
                }
            }
            __syncthreads();
        }
    }
    for(int i=tid;i<2048;i+=1024) g_keys[b*Nseq+i]=sk[i];
}

__global__ void softmax_rest_kernel(){
    __shared__ float sh[32];
    int b=blockIdx.x, tid=threadIdx.x;
    bool valid=tid<REST;
    float s=-__int_as_float(0x7f800000);
    if(valid){
        int idx=(int)(g_keys[b*Nseq+KTOP+tid]&0xffffffffu);
        s=g_scores[b*Nseq+idx];
    }
    float m=block_max(s,sh);
    float e=valid?expf(s-m):0.0f;
    float sum=block_sum(e,sh);
    g_w[b*1024+tid]=valid?(e/sum):0.0f;
}

__global__ void gather_kernel(float* __restrict__ out){
    int t=blockIdx.x*blockDim.x+threadIdx.x;
    if(t>=Bb*KTOP*256) return;
    int c4=t&255, r=t>>8, b=r/KTOP, i=r-b*KTOP;
    int idx=(int)(g_keys[b*Nseq+i]&0xffffffffu);
    size_t src=((size_t)(b*Nseq+idx))*1024+c4*4;
    size_t dst=((size_t)(b*OUTR+i))*1024+c4*4;
    *(float4*)(out+dst)=*(const float4*)(g_hs+src);
    *(float4*)(out+(size_t)Bb*OUTR*1024+dst)=*(const float4*)(g_res+src);
}

__global__ void fused_kernel(float* __restrict__ out){
    int b=blockIdx.x>>3, chunk=blockIdx.x&7;
    int col=chunk*128+threadIdx.x;
    float ah=0.f, ar=0.f;
    for(int i=0;i<REST;i++){
        int idx=(int)(g_keys[b*Nseq+KTOP+i]&0xffffffffu);
        float w=g_w[b*1024+i];
        size_t base=((size_t)(b*Nseq+idx))*1024+col;
        ah=fmaf(w,g_hs[base],ah);
        ar=fmaf(w,g_res[base],ar);
    }
    size_t dst=((size_t)(b*OUTR+KTOP))*1024+col;
    out[dst]=ah;
    out[(size_t)Bb*OUTR*1024+dst]=ar;
}

extern "C" void kernel_launch(void* const* d_in, const int* in_sizes, int n_in,
                              void* d_out, int out_size){
    const float* hidden=(const float*)d_in[0];
    const float* residual=(const float*)d_in[1];
    const float* norm_w=(const float*)d_in[2];
    const float* in_proj_w=(const float*)d_in[3];
    const float* conv_w=(const float*)d_in[4];
    const float* conv_b=(const float*)d_in[5];
    const float* x_proj_w=(const float*)d_in[6];
    const float* dt_proj_w=(const float*)d_in[7];
    const float* dt_proj_b=(const float*)d_in[8];
    const float* A_log=(const float*)d_in[9];
    const float* D_param=(const float*)d_in[10];
    const float* out_proj_w=(const float*)d_in[11];
    float* out=(float*)d_out;

    float *p_xn,*p_xz,*p_xc,*p_xdb,*p_dt,*p_y,*p_hs;
    cudaGetSymbolAddress((void**)&p_xn,g_xn);
    cudaGetSymbolAddress((void**)&p_xz,g_xz);
    cudaGetSymbolAddress((void**)&p_xc,g_xc);
    cudaGetSymbolAddress((void**)&p_xdb,g_xdb);
    cudaGetSymbolAddress((void**)&p_dt,g_dt);
    cudaGetSymbolAddress((void**)&p_y,g_y);
    cudaGetSymbolAddress((void**)&p_hs,g_hs);

    add_rmsnorm_kernel<<<Mrows,1024>>>(hidden,residual,norm_w);
    // in_proj: [4096 x 4096], K=1024  (dot2k near-CR fp32)
    dgemm_kernel<<<dim3(64,32),256>>>(p_xn,in_proj_w,p_xz,2*DI,Dd,Dd);
    conv_silu_kernel<<<(Mrows*DI)/256,256>>>(conv_w,conv_b);
    // x_proj: [4096 x 96], K=2048  (Kahan)
    kgemm_kernel<0><<<dim3(2,32),256>>>(p_xc,x_proj_w,p_xdb,nullptr,96,DI,DI);
    // dt: softplus([4096 x 2048] @ dtw^T + b), K=64, lda=96  (Kahan)
    kgemm_kernel<1><<<dim3(32,32),256>>>(p_xdb,dt_proj_w,p_dt,dt_proj_b,DI,64,96);
    scan_kernel<<<32,128>>>(A_log,D_param);
    // out_proj: [4096 x 1024], K=2048  (dot2k near-CR fp32)
    dgemm_kernel<<<dim3(16,32),256>>>(p_y,out_proj_w,p_hs,Dd,DI,DI);
    scores_kernel<<<Mrows,1024>>>();
    sort_kernel<<<Bb,1024>>>();
    softmax_rest_kernel<<<Bb,1024>>>();
    gather_kernel<<<(Bb*KTOP*256+255)/256,256>>>(out);
    fused_kernel<<<Bb*8,128>>>(out);
}

// round 15
// speedup vs baseline: 7.5127x; 1.0492x over previous
#include <cuda_runtime.h>
#include <math.h>

constexpr int Bb=2, Nseq=2048, Dd=1024, DI=2048, DS=16;
constexpr int Mrows=Bb*Nseq, KTOP=1434, REST=Nseq-KTOP, OUTR=KTOP+1;

__device__ float g_res[Mrows*Dd];
__device__ float g_xn [Mrows*Dd];
__device__ float g_xz [Mrows*2*DI];
__device__ float g_xc [Mrows*DI];
__device__ float g_xdb[Mrows*96];
__device__ float g_dt [Mrows*DI];
__device__ float g_y  [Mrows*DI];
__device__ float g_hs [Mrows*Dd];
__device__ float g_scores[Bb*Nseq];
__device__ unsigned long long g_keys[Bb*Nseq];
__device__ float g_w[Bb*1024];

typedef unsigned long long u64;
constexpr u64 SGN2 = 0x8000000080000000ull;

__device__ __forceinline__ u64 pk2(float lo, float hi){
    u64 r;
    asm("mov.b64 %0,{%1,%2};":"=l"(r):"r"(__float_as_uint(lo)),"r"(__float_as_uint(hi)));
    return r;
}
__device__ __forceinline__ void upk2(u64 v, float& lo, float& hi){
    unsigned a,b;
    asm("mov.b64 {%0,%1},%2;":"=r"(a),"=r"(b):"l"(v));
    lo=__uint_as_float(a); hi=__uint_as_float(b);
}
__device__ __forceinline__ u64 mul2(u64 a, u64 b){
    u64 r; asm("mul.rn.f32x2 %0,%1,%2;":"=l"(r):"l"(a),"l"(b)); return r;
}
__device__ __forceinline__ u64 add2(u64 a, u64 b){
    u64 r; asm("add.rn.f32x2 %0,%1,%2;":"=l"(r):"l"(a),"l"(b)); return r;
}
__device__ __forceinline__ u64 fma2(u64 a, u64 b, u64 c){
    u64 r; asm("fma.rn.f32x2 %0,%1,%2,%3;":"=l"(r):"l"(a),"l"(b),"l"(c)); return r;
}

__device__ __forceinline__ float warp_sum(float v){
#pragma unroll
    for(int o=16;o>0;o>>=1) v+=__shfl_xor_sync(0xffffffffu,v,o);
    return v;
}
__device__ __forceinline__ float warp_max(float v){
#pragma unroll
    for(int o=16;o>0;o>>=1) v=fmaxf(v,__shfl_xor_sync(0xffffffffu,v,o));
    return v;
}
__device__ __forceinline__ float block_sum(float v, float* sh){
    int lane=threadIdx.x&31, wid=threadIdx.x>>5, nw=blockDim.x>>5;
    v=warp_sum(v);
    if(lane==0) sh[wid]=v;
    __syncthreads();
    float t=(threadIdx.x<(unsigned)nw)?sh[threadIdx.x]:0.0f;
    if(wid==0){ t=warp_sum(t); if(lane==0) sh[0]=t; }
    __syncthreads(); float r=sh[0]; __syncthreads(); return r;
}
__device__ __forceinline__ float block_max(float v, float* sh){
    int lane=threadIdx.x&31, wid=threadIdx.x>>5, nw=blockDim.x>>5;
    v=warp_max(v);
    if(lane==0) sh[wid]=v;
    __syncthreads();
    float t=(threadIdx.x<(unsigned)nw)?sh[threadIdx.x]:-__int_as_float(0x7f800000);
    if(wid==0){ t=warp_max(t); if(lane==0) sh[0]=t; }
    __syncthreads(); float r=sh[0]; __syncthreads(); return r;
}
__device__ __forceinline__ float softplusf_(float x){
    return fmaxf(x,0.0f)+log1pf(expf(-fabsf(x)));
}
__device__ __forceinline__ float xla_tanhf(float x){
    if (fabsf(x) < 0.0004f) return x;
    float xc=fminf(fmaxf(x,-7.90531110763549805f),7.90531110763549805f);
    float x2=__fmul_rn(xc,xc);
    float p=-2.76076847742355e-16f;
    p=__fadd_rn(__fmul_rn(x2,p), 2.00018790482477e-13f);
    p=__fadd_rn(__fmul_rn(x2,p),-8.60467152213735e-11f);
    p=__fadd_rn(__fmul_rn(x2,p), 5.12229709037114e-08f);
    p=__fadd_rn(__fmul_rn(x2,p), 1.48572235717979e-05f);
    p=__fadd_rn(__fmul_rn(x2,p), 6.37261928875436e-04f);
    p=__fadd_rn(__fmul_rn(x2,p), 4.89352455891786e-03f);
    float num=__fmul_rn(xc,p);
    float q= 1.19825839466702e-06f;
    q=__fadd_rn(__fmul_rn(x2,q), 1.18534705686654e-04f);
    q=__fadd_rn(__fmul_rn(x2,q), 2.26843463243900e-03f);
    q=__fadd_rn(__fmul_rn(x2,q), 4.89352518554385e-03f);
    return __fdiv_rn(num,q);
}
__device__ __forceinline__ float silu_xla(float x){
    float t=xla_tanhf(__fmul_rn(0.5f,x));
    float sg=__fadd_rn(0.5f,__fmul_rn(0.5f,t));
    return __fmul_rn(x,sg);
}
__device__ __forceinline__ float tree_reduce_warp(float p){
#pragma unroll
    for(int off=16;off>0;off>>=1)
        p=__fadd_rn(p,__shfl_down_sync(0xffffffffu,p,off));
    return p;
}

// 1) add + rmsnorm (R13 config: 1024 thr x vec1 warp trees + rsqrtf)
__global__ void add_rmsnorm_kernel(const float* __restrict__ hs, const float* __restrict__ res,
                                   const float* __restrict__ w){
    __shared__ float sw[32];
    __shared__ float s_inv;
    int row=blockIdx.x, t=threadIdx.x;
    int lane=t&31, wid=t>>5;
    size_t base=(size_t)row*Dd+t;
    float v=__fadd_rn(hs[base],res[base]);
    g_res[base]=v;
    float p=__fmul_rn(v,v);
    p=tree_reduce_warp(p);
    if(lane==0) sw[wid]=p;
    __syncthreads();
    if(wid==0){
        float q=sw[lane];
        q=tree_reduce_warp(q);
        if(lane==0){
            float m=__fadd_rn(__fmul_rn(q,(1.0f/1024.0f)),1e-5f);
            s_inv=rsqrtf(m);
        }
    }
    __syncthreads();
    float inv=s_inv;
    g_xn[base]=__fmul_rn(__fmul_rn(v,inv),w[t]);
}

// dot2k GEMM, PACKED f32x2: bit-identical lanes to the scalar R14 version.
// Kahan state kept as (acc, ncmp=-cmp, nesum=-esum); subtraction realized as
// add of exactly-negated values (sign-XOR, exact).
__launch_bounds__(256,1)
__global__ void dgemm_kernel(const float* __restrict__ A, const float* __restrict__ Bw,
                             float* __restrict__ C, int Nc, int K, int lda){
    __shared__ __align__(16) float As[8][128];
    __shared__ __align__(16) float Bs[8][64];
    int tid=threadIdx.x, bx=blockIdx.x, by=blockIdx.y;
    int arow=tid>>1, ak4=(tid&1)<<2;
    const float* Ap=A+(size_t)(by*128+arow)*lda+ak4;
    int brow=(tid<128)?(tid>>1):0;
    const float* Bp=Bw+(size_t)(bx*64+brow)*K+ak4;
    int tx=tid&15, ty=tid>>4;
    u64 acc[8][2], ncmp[8][2], nesum[8][2];
#pragma unroll
    for(int i=0;i<8;i++)
#pragma unroll
        for(int j=0;j<2;j++){ acc[i][j]=0ull; ncmp[i][j]=0ull; nesum[i][j]=0ull; }
    for(int k0=0;k0<K;k0+=8){
        float4 av=*(const float4*)Ap; Ap+=8;
        float4 bv=make_float4(0.f,0.f,0.f,0.f);
        if(tid<128) bv=*(const float4*)Bp;
        Bp+=8;
        As[ak4+0][arow]=av.x; As[ak4+1][arow]=av.y;
        As[ak4+2][arow]=av.z; As[ak4+3][arow]=av.w;
        if(tid<128){
            Bs[ak4+0][brow]=bv.x; Bs[ak4+1][brow]=bv.y;
            Bs[ak4+2][brow]=bv.z; Bs[ak4+3][brow]=bv.w;
        }
        __syncthreads();
#pragma unroll
        for(int kk=0;kk<8;kk++){
            float ar_[8];
            *(float4*)(ar_)=*(const float4*)&As[kk][ty*8];
            *(float4*)(ar_+4)=*(const float4*)&As[kk][ty*8+4];
            float4 bq=*(const float4*)&Bs[kk][tx*4];
            u64 b2[2];
            b2[0]=pk2(bq.x,bq.y); b2[1]=pk2(bq.z,bq.w);
#pragma unroll
            for(int i=0;i<8;i++){
                u64 a2=pk2(ar_[i],ar_[i]);
                u64 na2=a2^SGN2;
#pragma unroll
                for(int j=0;j<2;j++){
                    u64 p=mul2(a2,b2[j]);
                    u64 e=fma2(na2,b2[j],p);          // p - a*b = -err (exact)
                    nesum[i][j]=add2(nesum[i][j],e);
                    u64 y=add2(p,ncmp[i][j]);          // p - cmp
                    u64 t=add2(acc[i][j],y);
                    u64 nt=t^SGN2;
                    u64 s1=add2(acc[i][j],nt);         // acc - t
                    ncmp[i][j]=add2(y,s1);             // y - (t - acc) = -cmp
                    acc[i][j]=t;
                }
            }
        }
        __syncthreads();
    }
#pragma unroll
    for(int i=0;i<8;i++){
        int row=by*128+ty*8+i, col=bx*64+tx*4;
        float4 o;
#pragma unroll
        for(int j=0;j<2;j++){
            u64 d=add2(ncmp[i][j],nesum[i][j]^SGN2);   // (-cmp) - (-esum) = esum - cmp
            u64 r=add2(acc[i][j],d);
            float lo,hi; upk2(r,lo,hi);
            if(j==0){ o.x=lo; o.y=hi; } else { o.z=lo; o.w=hi; }
        }
        *(float4*)(C+(size_t)row*Nc+col)=o;
    }
}

// Kahan GEMM (x_proj/dt; non-critical). EPI 0: none. EPI 1: softplus(acc+bias).
template <int EPI>
__launch_bounds__(256,1)
__global__ void kgemm_kernel(const float* __restrict__ A, const float* __restrict__ Bw,
                             float* __restrict__ C, const float* __restrict__ bias,
                             int Nc, int K, int lda){
    __shared__ __align__(16) float As[8][128];
    __shared__ __align__(16) float Bs[8][64];
    int tid=threadIdx.x, bx=blockIdx.x, by=blockIdx.y;
    int arow=tid>>1, ak4=(tid&1)<<2;
    const float* Ap=A+(size_t)(by*128+arow)*lda+ak4;
    int brow=(tid<128)?(tid>>1):0;
    int nrow=bx*64+brow;
    if(nrow>=Nc) nrow=Nc-1;
    const float* Bp=Bw+(size_t)nrow*K+ak4;
    int tx=tid&15, ty=tid>>4;
    float acc[8][4], car[8][4];
#pragma unroll
    for(int i=0;i<8;i++)
#pragma unroll
        for(int j=0;j<4;j++){ acc[i][j]=0.f; car[i][j]=0.f; }
    for(int k0=0;k0<K;k0+=8){
        float4 av=*(const float4*)Ap; Ap+=8;
        float4 bv=make_float4(0.f,0.f,0.f,0.f);
        if(tid<128) bv=*(const float4*)Bp;
        Bp+=8;
        As[ak4+0][arow]=av.x; As[ak4+1][arow]=av.y;
        As[ak4+2][arow]=av.z; As[ak4+3][arow]=av.w;
        if(tid<128){
            Bs[ak4+0][brow]=bv.x; Bs[ak4+1][brow]=bv.y;
            Bs[ak4+2][brow]=bv.z; Bs[ak4+3][brow]=bv.w;
        }
        __syncthreads();
        float pt[8][4];
#pragma unroll
        for(int i=0;i<8;i++)
#pragma unroll
            for(int j=0;j<4;j++) pt[i][j]=0.f;
#pragma unroll
        for(int kk=0;kk<8;kk++){
            float ar_[8], br_[4];
            *(float4*)(ar_)=*(const float4*)&As[kk][ty*8];
            *(float4*)(ar_+4)=*(const float4*)&As[kk][ty*8+4];
            *(float4*)(br_)=*(const float4*)&Bs[kk][tx*4];
#pragma unroll
            for(int i=0;i<8;i++)
#pragma unroll
                for(int j=0;j<4;j++) pt[i][j]=fmaf(ar_[i],br_[j],pt[i][j]);
        }
#pragma unroll
        for(int i=0;i<8;i++)
#pragma unroll
            for(int j=0;j<4;j++){
                float y=pt[i][j]-car[i][j];
                float t=acc[i][j]+y;
                car[i][j]=(t-acc[i][j])-y;
                acc[i][j]=t;
            }
        __syncthreads();
    }
#pragma unroll
    for(int i=0;i<8;i++){
        int row=by*128+ty*8+i, col=bx*64+tx*4;
        if(col+3<Nc){
            float4 o;
            if(EPI==1){
                o.x=softplusf_(__fadd_rn(acc[i][0]+car[i][0],bias[col+0]));
                o.y=softplusf_(__fadd_rn(acc[i][1]+car[i][1],bias[col+1]));
                o.z=softplusf_(__fadd_rn(acc[i][2]+car[i][2],bias[col+2]));
                o.w=softplusf_(__fadd_rn(acc[i][3]+car[i][3],bias[col+3]));
            } else {
                o.x=acc[i][0]+car[i][0]; o.y=acc[i][1]+car[i][1];
                o.z=acc[i][2]+car[i][2]; o.w=acc[i][3]+car[i][3];
            }
            *(float4*)(C+(size_t)row*Nc+col)=o;
        }
    }
}

// conv + XLA silu
__global__ void conv_silu_kernel(const float* __restrict__ cw, const float* __restrict__ cb){
    int idx=blockIdx.x*blockDim.x+threadIdx.x;
    if(idx>=Mrows*DI) return;
    int row=idx>>11, c=idx&(DI-1), n=row&(Nseq-1);
    float w0=cw[c*4+0], w1=cw[c*4+1], w2=cw[c*4+2], w3=cw[c*4+3];
    const float* xp=g_xz+(size_t)row*(2*DI)+c;
    float acc=0.0f;
    if(n>=3) acc=__fadd_rn(acc,__fmul_rn(xp[-3*(2*DI)],w0));
    if(n>=2) acc=__fadd_rn(acc,__fmul_rn(xp[-2*(2*DI)],w1));
    if(n>=1) acc=__fadd_rn(acc,__fmul_rn(xp[-1*(2*DI)],w2));
    acc=__fadd_rn(acc,__fmul_rn(xp[0],w3));
    acc=__fadd_rn(acc,cb[c]);
    g_xc[idx]=silu_xla(acc);
}

// scan: 16 lanes per channel (parallel states) — y-path realization proven
// irrelevant to output bits (R10 experiment), so tree-reduce is safe.
__global__ void scan_kernel(const float* __restrict__ A_log, const float* __restrict__ D_param){
    int tid=threadIdx.x, grp=tid>>4, s=tid&15;
    int g=blockIdx.x*16+grp, b=g>>11, d=g&(DI-1);
    float a=-expf(A_log[d*DS+s]);
    float Dp=D_param[d];
    float h=0.f;
    const float* dtp=g_dt+(size_t)(b*Nseq)*DI+d;
    const float* xcp=g_xc+(size_t)(b*Nseq)*DI+d;
    const float* zp =g_xz+(size_t)(b*Nseq)*(2*DI)+DI+d;
    const float* bcp=g_xdb+(size_t)(b*Nseq)*96+64+s;
    float* yp=g_y+(size_t)(b*Nseq)*DI+d;
    for(int n=0;n<Nseq;n++){
        float dtv=__ldg(dtp), xv=__ldg(xcp);
        float Bv=__ldg(bcp), Cv=__ldg(bcp+16);
        float dA=expf(dtv*a);
        h=fmaf(dA,h,dtv*xv*Bv);
        float yv=h*Cv;
        yv+=__shfl_xor_sync(0xffffffffu,yv,8);
        yv+=__shfl_xor_sync(0xffffffffu,yv,4);
        yv+=__shfl_xor_sync(0xffffffffu,yv,2);
        yv+=__shfl_xor_sync(0xffffffffu,yv,1);
        if(s==0){
            float zv=__ldg(zp);
            yp[0]=__fmul_rn(__fadd_rn(yv,__fmul_rn(Dp,xv)),silu_xla(zv));
        }
        dtp+=DI; xcp+=DI; zp+=2*DI; bcp+=96; yp+=DI;
    }
}

// scores (R13 config)
__global__ void scores_kernel(){
    __shared__ float sw[32];
    int row=blockIdx.x, t=threadIdx.x;
    int lane=t&31, wid=t>>5;
    float p=fmaxf(g_hs[(size_t)row*Dd+t],0.0f);
    p=tree_reduce_warp(p);
    if(lane==0) sw[wid]=p;
    __syncthreads();
    if(wid==0){
        float q=sw[lane];
        q=tree_reduce_warp(q);
        if(lane==0)
            g_scores[row]=(q==0.0f)?__int_as_float(0xff800000):q;
    }
}

__global__ void sort_kernel(){
    __shared__ unsigned long long sk[2048];
    int b=blockIdx.x, tid=threadIdx.x;
    for(int i=tid;i<2048;i+=1024){
        float s=g_scores[b*Nseq+i];
        unsigned u=__float_as_uint(s);
        unsigned ord=(u&0x80000000u)?~u:(u|0x80000000u);
        sk[i]=((unsigned long long)(~ord)<<32)|(unsigned)i;
    }
    __syncthreads();
    for(int k=2;k<=2048;k<<=1){
        for(int j=k>>1;j>0;j>>=1){
            for(int i=tid;i<2048;i+=1024){
                int ixj=i^j;
                if(ixj>i){
                    bool up=((i&k)==0);
                    unsigned long long x=sk[i], y=sk[ixj];
                    if((x>y)==up){ sk[i]=y; sk[ixj]=x; }
                }
            }
            __syncthreads();
        }
    }
    for(int i=tid;i<2048;i+=1024) g_keys[b*Nseq+i]=sk[i];
}

__global__ void softmax_rest_kernel(){
    __shared__ float sh[32];
    int b=blockIdx.x, tid=threadIdx.x;
    bool valid=tid<REST;
    float s=-__int_as_float(0x7f800000);
    if(valid){
        int idx=(int)(g_keys[b*Nseq+KTOP+tid]&0xffffffffu);
        s=g_scores[b*Nseq+idx];
    }
    float m=block_max(s,sh);
    float e=valid?expf(s-m):0.0f;
    float sum=block_sum(e,sh);
    g_w[b*1024+tid]=valid?(e/sum):0.0f;
}

__global__ void gather_kernel(float* __restrict__ out){
    int t=blockIdx.x*blockDim.x+threadIdx.x;
    if(t>=Bb*KTOP*256) return;
    int c4=t&255, r=t>>8, b=r/KTOP, i=r-b*KTOP;
    int idx=(int)(g_keys[b*Nseq+i]&0xffffffffu);
    size_t src=((size_t)(b*Nseq+idx))*1024+c4*4;
    size_t dst=((size_t)(b*OUTR+i))*1024+c4*4;
    *(float4*)(out+dst)=*(const float4*)(g_hs+src);
    *(float4*)(out+(size_t)Bb*OUTR*1024+dst)=*(const float4*)(g_res+src);
}

__global__ void fused_kernel(float* __restrict__ out){
    int b=blockIdx.x>>3, chunk=blockIdx.x&7;
    int col=chunk*128+threadIdx.x;
    float ah=0.f, ar=0.f;
    for(int i=0;i<REST;i++){
        int idx=(int)(g_keys[b*Nseq+KTOP+i]&0xffffffffu);
        float w=g_w[b*1024+i];
        size_t base=((size_t)(b*Nseq+idx))*1024+col;
        ah=fmaf(w,g_hs[base],ah);
        ar=fmaf(w,g_res[base],ar);
    }
    size_t dst=((size_t)(b*OUTR+KTOP))*1024+col;
    out[dst]=ah;
    out[(size_t)Bb*OUTR*1024+dst]=ar;
}

extern "C" void kernel_launch(void* const* d_in, const int* in_sizes, int n_in,
                              void* d_out, int out_size){
    const float* hidden=(const float*)d_in[0];
    const float* residual=(const float*)d_in[1];
    const float* norm_w=(const float*)d_in[2];
    const float* in_proj_w=(const float*)d_in[3];
    const float* conv_w=(const float*)d_in[4];
    const float* conv_b=(const float*)d_in[5];
    const float* x_proj_w=(const float*)d_in[6];
    const float* dt_proj_w=(const float*)d_in[7];
    const float* dt_proj_b=(const float*)d_in[8];
    const float* A_log=(const float*)d_in[9];
    const float* D_param=(const float*)d_in[10];
    const float* out_proj_w=(const float*)d_in[11];
    float* out=(float*)d_out;

    float *p_xn,*p_xz,*p_xc,*p_xdb,*p_dt,*p_y,*p_hs;
    cudaGetSymbolAddress((void**)&p_xn,g_xn);
    cudaGetSymbolAddress((void**)&p_xz,g_xz);
    cudaGetSymbolAddress((void**)&p_xc,g_xc);
    cudaGetSymbolAddress((void**)&p_xdb,g_xdb);
    cudaGetSymbolAddress((void**)&p_dt,g_dt);
    cudaGetSymbolAddress((void**)&p_y,g_y);
    cudaGetSymbolAddress((void**)&p_hs,g_hs);

    add_rmsnorm_kernel<<<Mrows,1024>>>(hidden,residual,norm_w);
    // in_proj: [4096 x 4096], K=1024  (packed dot2k)
    dgemm_kernel<<<dim3(64,32),256>>>(p_xn,in_proj_w,p_xz,2*DI,Dd,Dd);
    conv_silu_kernel<<<(Mrows*DI)/256,256>>>(conv_w,conv_b);
    // x_proj: [4096 x 96], K=2048  (Kahan)
    kgemm_kernel<0><<<dim3(2,32),256>>>(p_xc,x_proj_w,p_xdb,nullptr,96,DI,DI);
    // dt: softplus([4096 x 2048] @ dtw^T + b), K=64, lda=96  (Kahan)
    kgemm_kernel<1><<<dim3(32,32),256>>>(p_xdb,dt_proj_w,p_dt,dt_proj_b,DI,64,96);
    scan_kernel<<<(Bb*DI)/16,256>>>(A_log,D_param);
    // out_proj: [4096 x 1024], K=2048  (packed dot2k)
    dgemm_kernel<<<dim3(16,32),256>>>(p_y,out_proj_w,p_hs,Dd,DI,DI);
    scores_kernel<<<Mrows,1024>>>();
    sort_kernel<<<Bb,1024>>>();
    softmax_rest_kernel<<<Bb,1024>>>();
    gather_kernel<<<(Bb*KTOP*256+255)/256,256>>>(out);
    fused_kernel<<<Bb*8,128>>>(out);
}

// round 16
// speedup vs baseline: 10.0903x; 1.3431x over previous
#include <cuda_runtime.h>
#include <math.h>

constexpr int Bb=2, Nseq=2048, Dd=1024, DI=2048, DS=16;
constexpr int Mrows=Bb*Nseq, KTOP=1434, REST=Nseq-KTOP, OUTR=KTOP+1;

__device__ float g_res[Mrows*Dd];
__device__ float g_xn [Mrows*Dd];
__device__ float g_xz [Mrows*2*DI];
__device__ float g_xc [Mrows*DI];
__device__ float g_xdb[Mrows*96];
__device__ float g_dt [Mrows*DI];
__device__ float g_y  [Mrows*DI];
__device__ float g_hs [Mrows*Dd];
__device__ float g_scores[Bb*Nseq];
__device__ unsigned long long g_keys[Bb*Nseq];
__device__ float g_w[Bb*1024];
__device__ float g_nxn[Mrows];
__device__ float g_nw1[2*DI];
__device__ float g_ny [Mrows];
__device__ float g_nw2[Dd];

__device__ __forceinline__ float warp_sum(float v){
#pragma unroll
    for(int o=16;o>0;o>>=1) v+=__shfl_xor_sync(0xffffffffu,v,o);
    return v;
}
__device__ __forceinline__ float warp_max(float v){
#pragma unroll
    for(int o=16;o>0;o>>=1) v=fmaxf(v,__shfl_xor_sync(0xffffffffu,v,o));
    return v;
}
__device__ __forceinline__ float block_sum(float v, float* sh){
    int lane=threadIdx.x&31, wid=threadIdx.x>>5, nw=blockDim.x>>5;
    v=warp_sum(v);
    if(lane==0) sh[wid]=v;
    __syncthreads();
    float t=(threadIdx.x<(unsigned)nw)?sh[threadIdx.x]:0.0f;
    if(wid==0){ t=warp_sum(t); if(lane==0) sh[0]=t; }
    __syncthreads(); float r=sh[0]; __syncthreads(); return r;
}
__device__ __forceinline__ float block_max(float v, float* sh){
    int lane=threadIdx.x&31, wid=threadIdx.x>>5, nw=blockDim.x>>5;
    v=warp_max(v);
    if(lane==0) sh[wid]=v;
    __syncthreads();
    float t=(threadIdx.x<(unsigned)nw)?sh[threadIdx.x]:-__int_as_float(0x7f800000);
    if(wid==0){ t=warp_max(t); if(lane==0) sh[0]=t; }
    __syncthreads(); float r=sh[0]; __syncthreads(); return r;
}
__device__ __forceinline__ float softplusf_(float x){
    return fmaxf(x,0.0f)+log1pf(expf(-fabsf(x)));
}
__device__ __forceinline__ float xla_tanhf(float x){
    if (fabsf(x) < 0.0004f) return x;
    float xc=fminf(fmaxf(x,-7.90531110763549805f),7.90531110763549805f);
    float x2=__fmul_rn(xc,xc);
    float p=-2.76076847742355e-16f;
    p=__fadd_rn(__fmul_rn(x2,p), 2.00018790482477e-13f);
    p=__fadd_rn(__fmul_rn(x2,p),-8.60467152213735e-11f);
    p=__fadd_rn(__fmul_rn(x2,p), 5.12229709037114e-08f);
    p=__fadd_rn(__fmul_rn(x2,p), 1.48572235717979e-05f);
    p=__fadd_rn(__fmul_rn(x2,p), 6.37261928875436e-04f);
    p=__fadd_rn(__fmul_rn(x2,p), 4.89352455891786e-03f);
    float num=__fmul_rn(xc,p);
    float q= 1.19825839466702e-06f;
    q=__fadd_rn(__fmul_rn(x2,q), 1.18534705686654e-04f);
    q=__fadd_rn(__fmul_rn(x2,q), 2.26843463243900e-03f);
    q=__fadd_rn(__fmul_rn(x2,q), 4.89352518554385e-03f);
    return __fdiv_rn(num,q);
}
__device__ __forceinline__ float silu_xla(float x){
    float t=xla_tanhf(__fmul_rn(0.5f,x));
    float sg=__fadd_rn(0.5f,__fmul_rn(0.5f,t));
    return __fmul_rn(x,sg);
}
__device__ __forceinline__ float tree_reduce_warp(float p){
#pragma unroll
    for(int off=16;off>0;off>>=1)
        p=__fadd_rn(p,__shfl_down_sync(0xffffffffu,p,off));
    return p;
}
// strictly-greater power of two (exponent bump + mantissa clear)
__device__ __forceinline__ float pow2above(float x){
    unsigned u=(__float_as_uint(x)+0x00800000u)&0x7f800000u;
    return __uint_as_float(u);
}

// 1) add + rmsnorm (validated R13 config)
__global__ void add_rmsnorm_kernel(const float* __restrict__ hs, const float* __restrict__ res,
                                   const float* __restrict__ w){
    __shared__ float sw[32];
    __shared__ float s_inv;
    int row=blockIdx.x, t=threadIdx.x;
    int lane=t&31, wid=t>>5;
    size_t base=(size_t)row*Dd+t;
    float v=__fadd_rn(hs[base],res[base]);
    g_res[base]=v;
    float p=__fmul_rn(v,v);
    p=tree_reduce_warp(p);
    if(lane==0) sw[wid]=p;
    __syncthreads();
    if(wid==0){
        float q=sw[lane];
        q=tree_reduce_warp(q);
        if(lane==0){
            float m=__fadd_rn(__fmul_rn(q,(1.0f/1024.0f)),1e-5f);
            s_inv=rsqrtf(m);
        }
    }
    __syncthreads();
    float inv=s_inv;
    g_xn[base]=__fmul_rn(__fmul_rn(v,inv),w[t]);
}

// row L2 norms (upper-bound scale for grid-EFT; accuracy non-critical)
__global__ void norms_kernel(const float* __restrict__ X, float* __restrict__ out, int K){
    int warp=threadIdx.x>>5, lane=threadIdx.x&31;
    int row=blockIdx.x*8+warp;
    const float* p=X+(size_t)row*K;
    float s=0.0f;
    for(int i=lane;i<K;i+=32){ float v=p[i]; s=fmaf(v,v,s); }
    s=warp_sum(s);
    if(lane==0) out[row]=sqrtf(s);
}

// grid-EFT GEMM: 4 fma-pipe ops per MAC, error ~1e-4 ulp per element.
// acc pre-biased to 1.5*B (B = pow2 > 4*||a_row||*||b_col|| >= 4*sum|p|),
// so every t=fma(a,b,acc) rounds on a fixed grid; low bits captured exactly:
//   t=fma(a,b,acc); nd=acc-t (Sterbenz exact); e=fma(a,b,nd); elo+=e.
// Epilogue: (acc-init) exact + elo, one final rounding.
__launch_bounds__(256,1)
__global__ void dgemm_kernel(const float* __restrict__ A, const float* __restrict__ Bw,
                             float* __restrict__ C, const float* __restrict__ nA,
                             const float* __restrict__ nB, int Nc, int K, int lda){
    __shared__ __align__(16) float As[8][128];
    __shared__ __align__(16) float Bs[8][64];
    int tid=threadIdx.x, bx=blockIdx.x, by=blockIdx.y;
    int arow=tid>>1, ak4=(tid&1)<<2;
    const float* Ap=A+(size_t)(by*128+arow)*lda+ak4;
    int brow=(tid<128)?(tid>>1):0;
    const float* Bp=Bw+(size_t)(bx*64+brow)*K+ak4;
    int tx=tid&15, ty=tid>>4;
    float na[8], nb[4];
#pragma unroll
    for(int i=0;i<8;i++) na[i]=nA[by*128+ty*8+i];
#pragma unroll
    for(int j=0;j<4;j++) nb[j]=nB[bx*64+tx*4+j];
    float acc[8][4], elo[8][4];
#pragma unroll
    for(int i=0;i<8;i++)
#pragma unroll
        for(int j=0;j<4;j++){
            float Bg=pow2above(fmaxf(4.0f*na[i]*nb[j],1e-35f));
            acc[i][j]=1.5f*Bg;
            elo[i][j]=0.0f;
        }
    for(int k0=0;k0<K;k0+=8){
        float4 av=*(const float4*)Ap; Ap+=8;
        float4 bv=make_float4(0.f,0.f,0.f,0.f);
        if(tid<128) bv=*(const float4*)Bp;
        Bp+=8;
        As[ak4+0][arow]=av.x; As[ak4+1][arow]=av.y;
        As[ak4+2][arow]=av.z; As[ak4+3][arow]=av.w;
        if(tid<128){
            Bs[ak4+0][brow]=bv.x; Bs[ak4+1][brow]=bv.y;
            Bs[ak4+2][brow]=bv.z; Bs[ak4+3][brow]=bv.w;
        }
        __syncthreads();
#pragma unroll
        for(int kk=0;kk<8;kk++){
            float ar_[8], br_[4];
            *(float4*)(ar_)=*(const float4*)&As[kk][ty*8];
            *(float4*)(ar_+4)=*(const float4*)&As[kk][ty*8+4];
            *(float4*)(br_)=*(const float4*)&Bs[kk][tx*4];
#pragma unroll
            for(int i=0;i<8;i++)
#pragma unroll
                for(int j=0;j<4;j++){
                    float t=__fmaf_rn(ar_[i],br_[j],acc[i][j]);
                    float nd=__fsub_rn(acc[i][j],t);
                    float e=__fmaf_rn(ar_[i],br_[j],nd);
                    elo[i][j]=__fadd_rn(elo[i][j],e);
                    acc[i][j]=t;
                }
        }
        __syncthreads();
    }
#pragma unroll
    for(int i=0;i<8;i++){
        int row=by*128+ty*8+i, col=bx*64+tx*4;
        float4 o;
#pragma unroll
        for(int j=0;j<4;j++){
            float Bg=pow2above(fmaxf(4.0f*na[i]*nb[j],1e-35f));
            float hi=__fsub_rn(acc[i][j],1.5f*Bg);
            float r=__fadd_rn(hi,elo[i][j]);
            ((float*)&o)[j]=r;
        }
        *(float4*)(C+(size_t)row*Nc+col)=o;
    }
}

// Kahan GEMM (x_proj/dt; non-critical). EPI 0: none. EPI 1: softplus(acc+bias).
template <int EPI>
__launch_bounds__(256,1)
__global__ void kgemm_kernel(const float* __restrict__ A, const float* __restrict__ Bw,
                             float* __restrict__ C, const float* __restrict__ bias,
                             int Nc, int K, int lda){
    __shared__ __align__(16) float As[8][128];
    __shared__ __align__(16) float Bs[8][64];
    int tid=threadIdx.x, bx=blockIdx.x, by=blockIdx.y;
    int arow=tid>>1, ak4=(tid&1)<<2;
    const float* Ap=A+(size_t)(by*128+arow)*lda+ak4;
    int brow=(tid<128)?(tid>>1):0;
    int nrow=bx*64+brow;
    if(nrow>=Nc) nrow=Nc-1;
    const float* Bp=Bw+(size_t)nrow*K+ak4;
    int tx=tid&15, ty=tid>>4;
    float acc[8][4], car[8][4];
#pragma unroll
    for(int i=0;i<8;i++)
#pragma unroll
        for(int j=0;j<4;j++){ acc[i][j]=0.f; car[i][j]=0.f; }
    for(int k0=0;k0<K;k0+=8){
        float4 av=*(const float4*)Ap; Ap+=8;
        float4 bv=make_float4(0.f,0.f,0.f,0.f);
        if(tid<128) bv=*(const float4*)Bp;
        Bp+=8;
        As[ak4+0][arow]=av.x; As[ak4+1][arow]=av.y;
        As[ak4+2][arow]=av.z; As[ak4+3][arow]=av.w;
        if(tid<128){
            Bs[ak4+0][brow]=bv.x; Bs[ak4+1][brow]=bv.y;
            Bs[ak4+2][brow]=bv.z; Bs[ak4+3][brow]=bv.w;
        }
        __syncthreads();
        float pt[8][4];
#pragma unroll
        for(int i=0;i<8;i++)
#pragma unroll
            for(int j=0;j<4;j++) pt[i][j]=0.f;
#pragma unroll
        for(int kk=0;kk<8;kk++){
            float ar_[8], br_[4];
            *(float4*)(ar_)=*(const float4*)&As[kk][ty*8];
            *(float4*)(ar_+4)=*(const float4*)&As[kk][ty*8+4];
            *(float4*)(br_)=*(const float4*)&Bs[kk][tx*4];
#pragma unroll
            for(int i=0;i<8;i++)
#pragma unroll
                for(int j=0;j<4;j++) pt[i][j]=fmaf(ar_[i],br_[j],pt[i][j]);
        }
#pragma unroll
        for(int i=0;i<8;i++)
#pragma unroll
            for(int j=0;j<4;j++){
                float y=pt[i][j]-car[i][j];
                float t=acc[i][j]+y;
                car[i][j]=(t-acc[i][j])-y;
                acc[i][j]=t;
            }
        __syncthreads();
    }
#pragma unroll
    for(int i=0;i<8;i++){
        int row=by*128+ty*8+i, col=bx*64+tx*4;
        if(col+3<Nc){
            float4 o;
            if(EPI==1){
                o.x=softplusf_(__fadd_rn(acc[i][0]+car[i][0],bias[col+0]));
                o.y=softplusf_(__fadd_rn(acc[i][1]+car[i][1],bias[col+1]));
                o.z=softplusf_(__fadd_rn(acc[i][2]+car[i][2],bias[col+2]));
                o.w=softplusf_(__fadd_rn(acc[i][3]+car[i][3],bias[col+3]));
            } else {
                o.x=acc[i][0]+car[i][0]; o.y=acc[i][1]+car[i][1];
                o.z=acc[i][2]+car[i][2]; o.w=acc[i][3]+car[i][3];
            }
            *(float4*)(C+(size_t)row*Nc+col)=o;
        }
    }
}

// conv + XLA silu
__global__ void conv_silu_kernel(const float* __restrict__ cw, const float* __restrict__ cb){
    int idx=blockIdx.x*blockDim.x+threadIdx.x;
    if(idx>=Mrows*DI) return;
    int row=idx>>11, c=idx&(DI-1), n=row&(Nseq-1);
    float w0=cw[c*4+0], w1=cw[c*4+1], w2=cw[c*4+2], w3=cw[c*4+3];
    const float* xp=g_xz+(size_t)row*(2*DI)+c;
    float acc=0.0f;
    if(n>=3) acc=__fadd_rn(acc,__fmul_rn(xp[-3*(2*DI)],w0));
    if(n>=2) acc=__fadd_rn(acc,__fmul_rn(xp[-2*(2*DI)],w1));
    if(n>=1) acc=__fadd_rn(acc,__fmul_rn(xp[-1*(2*DI)],w2));
    acc=__fadd_rn(acc,__fmul_rn(xp[0],w3));
    acc=__fadd_rn(acc,cb[c]);
    g_xc[idx]=silu_xla(acc);
}

// scan: 16 lanes per channel (R15 config — y-path realization proven bit-irrelevant)
__global__ void scan_kernel(const float* __restrict__ A_log, const float* __restrict__ D_param){
    int tid=threadIdx.x, grp=tid>>4, s=tid&15;
    int g=blockIdx.x*16+grp, b=g>>11, d=g&(DI-1);
    float a=-expf(A_log[d*DS+s]);
    float Dp=D_param[d];
    float h=0.f;
    const float* dtp=g_dt+(size_t)(b*Nseq)*DI+d;
    const float* xcp=g_xc+(size_t)(b*Nseq)*DI+d;
    const float* zp =g_xz+(size_t)(b*Nseq)*(2*DI)+DI+d;
    const float* bcp=g_xdb+(size_t)(b*Nseq)*96+64+s;
    float* yp=g_y+(size_t)(b*Nseq)*DI+d;
    for(int n=0;n<Nseq;n++){
        float dtv=__ldg(dtp), xv=__ldg(xcp);
        float Bv=__ldg(bcp), Cv=__ldg(bcp+16);
        float dA=expf(dtv*a);
        h=fmaf(dA,h,dtv*xv*Bv);
        float yv=h*Cv;
        yv+=__shfl_xor_sync(0xffffffffu,yv,8);
        yv+=__shfl_xor_sync(0xffffffffu,yv,4);
        yv+=__shfl_xor_sync(0xffffffffu,yv,2);
        yv+=__shfl_xor_sync(0xffffffffu,yv,1);
        if(s==0){
            float zv=__ldg(zp);
            yp[0]=__fmul_rn(__fadd_rn(yv,__fmul_rn(Dp,xv)),silu_xla(zv));
        }
        dtp+=DI; xcp+=DI; zp+=2*DI; bcp+=96; yp+=DI;
    }
}

// scores (validated R13 config)
__global__ void scores_kernel(){
    __shared__ float sw[32];
    int row=blockIdx.x, t=threadIdx.x;
    int lane=t&31, wid=t>>5;
    float p=fmaxf(g_hs[(size_t)row*Dd+t],0.0f);
    p=tree_reduce_warp(p);
    if(lane==0) sw[wid]=p;
    __syncthreads();
    if(wid==0){
        float q=sw[lane];
        q=tree_reduce_warp(q);
        if(lane==0)
            g_scores[row]=(q==0.0f)?__int_as_float(0xff800000):q;
    }
}

__global__ void sort_kernel(){
    __shared__ unsigned long long sk[2048];
    int b=blockIdx.x, tid=threadIdx.x;
    for(int i=tid;i<2048;i+=1024){
        float s=g_scores[b*Nseq+i];
        unsigned u=__float_as_uint(s);
        unsigned ord=(u&0x80000000u)?~u:(u|0x80000000u);
        sk[i]=((unsigned long long)(~ord)<<32)|(unsigned)i;
    }
    __syncthreads();
    for(int k=2;k<=2048;k<<=1){
        for(int j=k>>1;j>0;j>>=1){
            for(int i=tid;i<2048;i+=1024){
                int ixj=i^j;
                if(ixj>i){
                    bool up=((i&k)==0);
                    unsigned long long x=sk[i], y=sk[ixj];
                    if((x>y)==up){ sk[i]=y; sk[ixj]=x; }
                }
            }
            __syncthreads();
        }
    }
    for(int i=tid;i<2048;i+=1024) g_keys[b*Nseq+i]=sk[i];
}

__global__ void softmax_rest_kernel(){
    __shared__ float sh[32];
    int b=blockIdx.x, tid=threadIdx.x;
    bool valid=tid<REST;
    float s=-__int_as_float(0x7f800000);
    if(valid){
        int idx=(int)(g_keys[b*Nseq+KTOP+tid]&0xffffffffu);
        s=g_scores[b*Nseq+idx];
    }
    float m=block_max(s,sh);
    float e=valid?expf(s-m):0.0f;
    float sum=block_sum(e,sh);
    g_w[b*1024+tid]=valid?(e/sum):0.0f;
}

__global__ void gather_kernel(float* __restrict__ out){
    int t=blockIdx.x*blockDim.x+threadIdx.x;
    if(t>=Bb*KTOP*256) return;
    int c4=t&255, r=t>>8, b=r/KTOP, i=r-b*KTOP;
    int idx=(int)(g_keys[b*Nseq+i]&0xffffffffu);
    size_t src=((size_t)(b*Nseq+idx))*1024+c4*4;
    size_t dst=((size_t)(b*OUTR+i))*1024+c4*4;
    *(float4*)(out+dst)=*(const float4*)(g_hs+src);
    *(float4*)(out+(size_t)Bb*OUTR*1024+dst)=*(const float4*)(g_res+src);
}

__global__ void fused_kernel(float* __restrict__ out){
    int b=blockIdx.x>>3, chunk=blockIdx.x&7;
    int col=chunk*128+threadIdx.x;
    float ah=0.f, ar=0.f;
    for(int i=0;i<REST;i++){
        int idx=(int)(g_keys[b*Nseq+KTOP+i]&0xffffffffu);
        float w=g_w[b*1024+i];
        size_t base=((size_t)(b*Nseq+idx))*1024+col;
        ah=fmaf(w,g_hs[base],ah);
        ar=fmaf(w,g_res[base],ar);
    }
    size_t dst=((size_t)(b*OUTR+KTOP))*1024+col;
    out[dst]=ah;
    out[(size_t)Bb*OUTR*1024+dst]=ar;
}

extern "C" void kernel_launch(void* const* d_in, const int* in_sizes, int n_in,
                              void* d_out, int out_size){
    const float* hidden=(const float*)d_in[0];
    const float* residual=(const float*)d_in[1];
    const float* norm_w=(const float*)d_in[2];
    const float* in_proj_w=(const float*)d_in[3];
    const float* conv_w=(const float*)d_in[4];
    const float* conv_b=(const float*)d_in[5];
    const float* x_proj_w=(const float*)d_in[6];
    const float* dt_proj_w=(const float*)d_in[7];
    const float* dt_proj_b=(const float*)d_in[8];
    const float* A_log=(const float*)d_in[9];
    const float* D_param=(const float*)d_in[10];
    const float* out_proj_w=(const float*)d_in[11];
    float* out=(float*)d_out;

    float *p_xn,*p_xz,*p_xc,*p_xdb,*p_dt,*p_y,*p_hs;
    float *p_nxn,*p_nw1,*p_ny,*p_nw2;
    cudaGetSymbolAddress((void**)&p_xn,g_xn);
    cudaGetSymbolAddress((void**)&p_xz,g_xz);
    cudaGetSymbolAddress((void**)&p_xc,g_xc);
    cudaGetSymbolAddress((void**)&p_xdb,g_xdb);
    cudaGetSymbolAddress((void**)&p_dt,g_dt);
    cudaGetSymbolAddress((void**)&p_y,g_y);
    cudaGetSymbolAddress((void**)&p_hs,g_hs);
    cudaGetSymbolAddress((void**)&p_nxn,g_nxn);
    cudaGetSymbolAddress((void**)&p_nw1,g_nw1);
    cudaGetSymbolAddress((void**)&p_ny,g_ny);
    cudaGetSymbolAddress((void**)&p_nw2,g_nw2);

    add_rmsnorm_kernel<<<Mrows,1024>>>(hidden,residual,norm_w);
    // row norms for grid-EFT scales
    norms_kernel<<<(2*DI)/8,256>>>(in_proj_w,p_nw1,Dd);
    norms_kernel<<<Dd/8,256>>>(out_proj_w,p_nw2,DI);
    norms_kernel<<<Mrows/8,256>>>(p_xn,p_nxn,Dd);
    // in_proj: [4096 x 4096], K=1024  (grid-EFT, 4 ops/MAC)
    dgemm_kernel<<<dim3(64,32),256>>>(p_xn,in_proj_w,p_xz,p_nxn,p_nw1,2*DI,Dd,Dd);
    conv_silu_kernel<<<(Mrows*DI)/256,256>>>(conv_w,conv_b);
    // x_proj: [4096 x 96], K=2048  (Kahan)
    kgemm_kernel<0><<<dim3(2,32),256>>>(p_xc,x_proj_w,p_xdb,nullptr,96,DI,DI);
    // dt: softplus([4096 x 2048] @ dtw^T + b), K=64, lda=96  (Kahan)
    kgemm_kernel<1><<<dim3(32,32),256>>>(p_xdb,dt_proj_w,p_dt,dt_proj_b,DI,64,96);
    scan_kernel<<<(Bb*DI)/16,256>>>(A_log,D_param);
    norms_kernel<<<Mrows/8,256>>>(p_y,p_ny,DI);
    // out_proj: [4096 x 1024], K=2048  (grid-EFT)
    dgemm_kernel<<<dim3(16,32),256>>>(p_y,out_proj_w,p_hs,p_ny,p_nw2,Dd,DI,DI);
    scores_kernel<<<Mrows,1024>>>();
    sort_kernel<<<Bb,1024>>>();
    softmax_rest_kernel<<<Bb,1024>>>();
    gather_kernel<<<(Bb*KTOP*256+255)/256,256>>>(out);
    fused_kernel<<<Bb*8,128>>>(out);
}

// round 17
// speedup vs baseline: 11.1962x; 1.1096x over previous
#include <cuda_runtime.h>
#include <math.h>

constexpr int Bb=2, Nseq=2048, Dd=1024, DI=2048, DS=16;
constexpr int Mrows=Bb*Nseq, KTOP=1434, REST=Nseq-KTOP, OUTR=KTOP+1;

__device__ float g_res[Mrows*Dd];
__device__ float g_xn [Mrows*Dd];
__device__ float g_xz [Mrows*2*DI];
__device__ float g_xc [Mrows*DI];
__device__ float g_xdb[Mrows*96];
__device__ float g_dt [Mrows*DI];
__device__ float g_y  [Mrows*DI];
__device__ float g_hs [Mrows*Dd];
__device__ float g_scores[Bb*Nseq];
__device__ unsigned long long g_keys[Bb*Nseq];
__device__ float g_w[Bb*1024];
__device__ float g_nxn[Mrows];
__device__ float g_nw1[2*DI];
__device__ float g_ny [Mrows];
__device__ float g_nw2[Dd];

__device__ __forceinline__ float warp_sum(float v){
#pragma unroll
    for(int o=16;o>0;o>>=1) v+=__shfl_xor_sync(0xffffffffu,v,o);
    return v;
}
__device__ __forceinline__ float warp_max(float v){
#pragma unroll
    for(int o=16;o>0;o>>=1) v=fmaxf(v,__shfl_xor_sync(0xffffffffu,v,o));
    return v;
}
__device__ __forceinline__ float block_sum(float v, float* sh){
    int lane=threadIdx.x&31, wid=threadIdx.x>>5, nw=blockDim.x>>5;
    v=warp_sum(v);
    if(lane==0) sh[wid]=v;
    __syncthreads();
    float t=(threadIdx.x<(unsigned)nw)?sh[threadIdx.x]:0.0f;
    if(wid==0){ t=warp_sum(t); if(lane==0) sh[0]=t; }
    __syncthreads(); float r=sh[0]; __syncthreads(); return r;
}
__device__ __forceinline__ float block_max(float v, float* sh){
    int lane=threadIdx.x&31, wid=threadIdx.x>>5, nw=blockDim.x>>5;
    v=warp_max(v);
    if(lane==0) sh[wid]=v;
    __syncthreads();
    float t=(threadIdx.x<(unsigned)nw)?sh[threadIdx.x]:-__int_as_float(0x7f800000);
    if(wid==0){ t=warp_max(t); if(lane==0) sh[0]=t; }
    __syncthreads(); float r=sh[0]; __syncthreads(); return r;
}
__device__ __forceinline__ float softplusf_(float x){
    return fmaxf(x,0.0f)+log1pf(expf(-fabsf(x)));
}
__device__ __forceinline__ float xla_tanhf(float x){
    if (fabsf(x) < 0.0004f) return x;
    float xc=fminf(fmaxf(x,-7.90531110763549805f),7.90531110763549805f);
    float x2=__fmul_rn(xc,xc);
    float p=-2.76076847742355e-16f;
    p=__fadd_rn(__fmul_rn(x2,p), 2.00018790482477e-13f);
    p=__fadd_rn(__fmul_rn(x2,p),-8.60467152213735e-11f);
    p=__fadd_rn(__fmul_rn(x2,p), 5.12229709037114e-08f);
    p=__fadd_rn(__fmul_rn(x2,p), 1.48572235717979e-05f);
    p=__fadd_rn(__fmul_rn(x2,p), 6.37261928875436e-04f);
    p=__fadd_rn(__fmul_rn(x2,p), 4.89352455891786e-03f);
    float num=__fmul_rn(xc,p);
    float q= 1.19825839466702e-06f;
    q=__fadd_rn(__fmul_rn(x2,q), 1.18534705686654e-04f);
    q=__fadd_rn(__fmul_rn(x2,q), 2.26843463243900e-03f);
    q=__fadd_rn(__fmul_rn(x2,q), 4.89352518554385e-03f);
    return __fdiv_rn(num,q);
}
__device__ __forceinline__ float silu_xla(float x){
    float t=xla_tanhf(__fmul_rn(0.5f,x));
    float sg=__fadd_rn(0.5f,__fmul_rn(0.5f,t));
    return __fmul_rn(x,sg);
}
__device__ __forceinline__ float tree_reduce_warp(float p){
#pragma unroll
    for(int off=16;off>0;off>>=1)
        p=__fadd_rn(p,__shfl_down_sync(0xffffffffu,p,off));
    return p;
}
__device__ __forceinline__ float pow2above(float x){
    unsigned u=(__float_as_uint(x)+0x00800000u)&0x7f800000u;
    return __uint_as_float(u);
}

// 1) add + rmsnorm (validated R13 config)
__global__ void add_rmsnorm_kernel(const float* __restrict__ hs, const float* __restrict__ res,
                                   const float* __restrict__ w){
    __shared__ float sw[32];
    __shared__ float s_inv;
    int row=blockIdx.x, t=threadIdx.x;
    int lane=t&31, wid=t>>5;
    size_t base=(size_t)row*Dd+t;
    float v=__fadd_rn(hs[base],res[base]);
    g_res[base]=v;
    float p=__fmul_rn(v,v);
    p=tree_reduce_warp(p);
    if(lane==0) sw[wid]=p;
    __syncthreads();
    if(wid==0){
        float q=sw[lane];
        q=tree_reduce_warp(q);
        if(lane==0){
            float m=__fadd_rn(__fmul_rn(q,(1.0f/1024.0f)),1e-5f);
            s_inv=rsqrtf(m);
        }
    }
    __syncthreads();
    float inv=s_inv;
    g_xn[base]=__fmul_rn(__fmul_rn(v,inv),w[t]);
}

// row L2 norms (scale bound for grid-EFT)
__global__ void norms_kernel(const float* __restrict__ X, float* __restrict__ out, int K){
    int warp=threadIdx.x>>5, lane=threadIdx.x&31;
    int row=blockIdx.x*8+warp;
    const float* p=X+(size_t)row*K;
    float s=0.0f;
    for(int i=lane;i<K;i+=32){ float v=p[i]; s=fmaf(v,v,s); }
    s=warp_sum(s);
    if(lane==0) out[row]=sqrtf(s);
}

// grid-EFT GEMM: 4 fma-pipe ops/MAC, ~1e-4 ulp elements. KTILE=16, occ=2.
__launch_bounds__(256,2)
__global__ void dgemm_kernel(const float* __restrict__ A, const float* __restrict__ Bw,
                             float* __restrict__ C, const float* __restrict__ nA,
                             const float* __restrict__ nB, int Nc, int K, int lda){
    __shared__ __align__(16) float As[16][128];
    __shared__ __align__(16) float Bs[16][64];
    int tid=threadIdx.x, bx=blockIdx.x, by=blockIdx.y;
    int arow=tid>>1, ak8=(tid&1)<<3;                   // 8 consecutive k per thread
    const float* Ap=A+(size_t)(by*128+arow)*lda+ak8;
    int brow=(tid<128)?(tid>>1):0;
    const float* Bp=Bw+(size_t)(bx*64+brow)*K+ak8;
    int tx=tid&15, ty=tid>>4;
    float na[8], nb[4];
#pragma unroll
    for(int i=0;i<8;i++) na[i]=nA[by*128+ty*8+i];
#pragma unroll
    for(int j=0;j<4;j++) nb[j]=nB[bx*64+tx*4+j];
    float acc[8][4], elo[8][4];
#pragma unroll
    for(int i=0;i<8;i++)
#pragma unroll
        for(int j=0;j<4;j++){
            float Bg=pow2above(fmaxf(4.0f*na[i]*nb[j],1e-35f));
            acc[i][j]=1.5f*Bg;
            elo[i][j]=0.0f;
        }
    for(int k0=0;k0<K;k0+=16){
        float4 a0=*(const float4*)Ap;
        float4 a1=*(const float4*)(Ap+4);
        Ap+=16;
        float4 b0=make_float4(0.f,0.f,0.f,0.f), b1=b0;
        if(tid<128){ b0=*(const float4*)Bp; b1=*(const float4*)(Bp+4); }
        Bp+=16;
        As[ak8+0][arow]=a0.x; As[ak8+1][arow]=a0.y;
        As[ak8+2][arow]=a0.z; As[ak8+3][arow]=a0.w;
        As[ak8+4][arow]=a1.x; As[ak8+5][arow]=a1.y;
        As[ak8+6][arow]=a1.z; As[ak8+7][arow]=a1.w;
        if(tid<128){
            Bs[ak8+0][brow]=b0.x; Bs[ak8+1][brow]=b0.y;
            Bs[ak8+2][brow]=b0.z; Bs[ak8+3][brow]=b0.w;
            Bs[ak8+4][brow]=b1.x; Bs[ak8+5][brow]=b1.y;
            Bs[ak8+6][brow]=b1.z; Bs[ak8+7][brow]=b1.w;
        }
        __syncthreads();
#pragma unroll
        for(int kk=0;kk<16;kk++){
            float ar_[8], br_[4];
            *(float4*)(ar_)=*(const float4*)&As[kk][ty*8];
            *(float4*)(ar_+4)=*(const float4*)&As[kk][ty*8+4];
            *(float4*)(br_)=*(const float4*)&Bs[kk][tx*4];
#pragma unroll
            for(int i=0;i<8;i++)
#pragma unroll
                for(int j=0;j<4;j++){
                    float t=__fmaf_rn(ar_[i],br_[j],acc[i][j]);
                    float nd=__fsub_rn(acc[i][j],t);
                    float e=__fmaf_rn(ar_[i],br_[j],nd);
                    elo[i][j]=__fadd_rn(elo[i][j],e);
                    acc[i][j]=t;
                }
        }
        __syncthreads();
    }
#pragma unroll
    for(int i=0;i<8;i++){
        int row=by*128+ty*8+i, col=bx*64+tx*4;
        float4 o;
#pragma unroll
        for(int j=0;j<4;j++){
            float Bg=pow2above(fmaxf(4.0f*na[i]*nb[j],1e-35f));
            float hi=__fsub_rn(acc[i][j],1.5f*Bg);
            ((float*)&o)[j]=__fadd_rn(hi,elo[i][j]);
        }
        *(float4*)(C+(size_t)row*Nc+col)=o;
    }
}

// Kahan GEMM (x_proj/dt). EPI 0: none. EPI 1: softplus(acc+bias).
template <int EPI>
__launch_bounds__(256,1)
__global__ void kgemm_kernel(const float* __restrict__ A, const float* __restrict__ Bw,
                             float* __restrict__ C, const float* __restrict__ bias,
                             int Nc, int K, int lda){
    __shared__ __align__(16) float As[8][128];
    __shared__ __align__(16) float Bs[8][64];
    int tid=threadIdx.x, bx=blockIdx.x, by=blockIdx.y;
    int arow=tid>>1, ak4=(tid&1)<<2;
    const float* Ap=A+(size_t)(by*128+arow)*lda+ak4;
    int brow=(tid<128)?(tid>>1):0;
    int nrow=bx*64+brow;
    if(nrow>=Nc) nrow=Nc-1;
    const float* Bp=Bw+(size_t)nrow*K+ak4;
    int tx=tid&15, ty=tid>>4;
    float acc[8][4], car[8][4];
#pragma unroll
    for(int i=0;i<8;i++)
#pragma unroll
        for(int j=0;j<4;j++){ acc[i][j]=0.f; car[i][j]=0.f; }
    for(int k0=0;k0<K;k0+=8){
        float4 av=*(const float4*)Ap; Ap+=8;
        float4 bv=make_float4(0.f,0.f,0.f,0.f);
        if(tid<128) bv=*(const float4*)Bp;
        Bp+=8;
        As[ak4+0][arow]=av.x; As[ak4+1][arow]=av.y;
        As[ak4+2][arow]=av.z; As[ak4+3][arow]=av.w;
        if(tid<128){
            Bs[ak4+0][brow]=bv.x; Bs[ak4+1][brow]=bv.y;
            Bs[ak4+2][brow]=bv.z; Bs[ak4+3][brow]=bv.w;
        }
        __syncthreads();
        float pt[8][4];
#pragma unroll
        for(int i=0;i<8;i++)
#pragma unroll
            for(int j=0;j<4;j++) pt[i][j]=0.f;
#pragma unroll
        for(int kk=0;kk<8;kk++){
            float ar_[8], br_[4];
            *(float4*)(ar_)=*(const float4*)&As[kk][ty*8];
            *(float4*)(ar_+4)=*(const float4*)&As[kk][ty*8+4];
            *(float4*)(br_)=*(const float4*)&Bs[kk][tx*4];
#pragma unroll
            for(int i=0;i<8;i++)
#pragma unroll
                for(int j=0;j<4;j++) pt[i][j]=fmaf(ar_[i],br_[j],pt[i][j]);
        }
#pragma unroll
        for(int i=0;i<8;i++)
#pragma unroll
            for(int j=0;j<4;j++){
                float y=pt[i][j]-car[i][j];
                float t=acc[i][j]+y;
                car[i][j]=(t-acc[i][j])-y;
                acc[i][j]=t;
            }
        __syncthreads();
    }
#pragma unroll
    for(int i=0;i<8;i++){
        int row=by*128+ty*8+i, col=bx*64+tx*4;
        if(col+3<Nc){
            float4 o;
            if(EPI==1){
                o.x=softplusf_(__fadd_rn(acc[i][0]+car[i][0],bias[col+0]));
                o.y=softplusf_(__fadd_rn(acc[i][1]+car[i][1],bias[col+1]));
                o.z=softplusf_(__fadd_rn(acc[i][2]+car[i][2],bias[col+2]));
                o.w=softplusf_(__fadd_rn(acc[i][3]+car[i][3],bias[col+3]));
            } else {
                o.x=acc[i][0]+car[i][0]; o.y=acc[i][1]+car[i][1];
                o.z=acc[i][2]+car[i][2]; o.w=acc[i][3]+car[i][3];
            }
            *(float4*)(C+(size_t)row*Nc+col)=o;
        }
    }
}

// conv + XLA silu
__global__ void conv_silu_kernel(const float* __restrict__ cw, const float* __restrict__ cb){
    int idx=blockIdx.x*blockDim.x+threadIdx.x;
    if(idx>=Mrows*DI) return;
    int row=idx>>11, c=idx&(DI-1), n=row&(Nseq-1);
    float w0=cw[c*4+0], w1=cw[c*4+1], w2=cw[c*4+2], w3=cw[c*4+3];
    const float* xp=g_xz+(size_t)row*(2*DI)+c;
    float acc=0.0f;
    if(n>=3) acc=__fadd_rn(acc,__fmul_rn(xp[-3*(2*DI)],w0));
    if(n>=2) acc=__fadd_rn(acc,__fmul_rn(xp[-2*(2*DI)],w1));
    if(n>=1) acc=__fadd_rn(acc,__fmul_rn(xp[-1*(2*DI)],w2));
    acc=__fadd_rn(acc,__fmul_rn(xp[0],w3));
    acc=__fadd_rn(acc,cb[c]);
    g_xc[idx]=silu_xla(acc);
}

// scan: 16 lanes per channel
__global__ void scan_kernel(const float* __restrict__ A_log, const float* __restrict__ D_param){
    int tid=threadIdx.x, grp=tid>>4, s=tid&15;
    int g=blockIdx.x*16+grp, b=g>>11, d=g&(DI-1);
    float a=-expf(A_log[d*DS+s]);
    float Dp=D_param[d];
    float h=0.f;
    const float* dtp=g_dt+(size_t)(b*Nseq)*DI+d;
    const float* xcp=g_xc+(size_t)(b*Nseq)*DI+d;
    const float* zp =g_xz+(size_t)(b*Nseq)*(2*DI)+DI+d;
    const float* bcp=g_xdb+(size_t)(b*Nseq)*96+64+s;
    float* yp=g_y+(size_t)(b*Nseq)*DI+d;
    for(int n=0;n<Nseq;n++){
        float dtv=__ldg(dtp), xv=__ldg(xcp);
        float Bv=__ldg(bcp), Cv=__ldg(bcp+16);
        float dA=expf(dtv*a);
        h=fmaf(dA,h,dtv*xv*Bv);
        float yv=h*Cv;
        yv+=__shfl_xor_sync(0xffffffffu,yv,8);
        yv+=__shfl_xor_sync(0xffffffffu,yv,4);
        yv+=__shfl_xor_sync(0xffffffffu,yv,2);
        yv+=__shfl_xor_sync(0xffffffffu,yv,1);
        if(s==0){
            float zv=__ldg(zp);
            yp[0]=__fmul_rn(__fadd_rn(yv,__fmul_rn(Dp,xv)),silu_xla(zv));
        }
        dtp+=DI; xcp+=DI; zp+=2*DI; bcp+=96; yp+=DI;
    }
}

// scores (validated R13 config)
__global__ void scores_kernel(){
    __shared__ float sw[32];
    int row=blockIdx.x, t=threadIdx.x;
    int lane=t&31, wid=t>>5;
    float p=fmaxf(g_hs[(size_t)row*Dd+t],0.0f);
    p=tree_reduce_warp(p);
    if(lane==0) sw[wid]=p;
    __syncthreads();
    if(wid==0){
        float q=sw[lane];
        q=tree_reduce_warp(q);
        if(lane==0)
            g_scores[row]=(q==0.0f)?__int_as_float(0xff800000):q;
    }
}

__global__ void sort_kernel(){
    __shared__ unsigned long long sk[2048];
    int b=blockIdx.x, tid=threadIdx.x;
    for(int i=tid;i<2048;i+=1024){
        float s=g_scores[b*Nseq+i];
        unsigned u=__float_as_uint(s);
        unsigned ord=(u&0x80000000u)?~u:(u|0x80000000u);
        sk[i]=((unsigned long long)(~ord)<<32)|(unsigned)i;
    }
    __syncthreads();
    for(int k=2;k<=2048;k<<=1){
        for(int j=k>>1;j>0;j>>=1){
            for(int i=tid;i<2048;i+=1024){
                int ixj=i^j;
                if(ixj>i){
                    bool up=((i&k)==0);
                    unsigned long long x=sk[i], y=sk[ixj];
                    if((x>y)==up){ sk[i]=y; sk[ixj]=x; }
                }
            }
            __syncthreads();
        }
    }
    for(int i=tid;i<2048;i+=1024) g_keys[b*Nseq+i]=sk[i];
}

__global__ void softmax_rest_kernel(){
    __shared__ float sh[32];
    int b=blockIdx.x, tid=threadIdx.x;
    bool valid=tid<REST;
    float s=-__int_as_float(0x7f800000);
    if(valid){
        int idx=(int)(g_keys[b*Nseq+KTOP+tid]&0xffffffffu);
        s=g_scores[b*Nseq+idx];
    }
    float m=block_max(s,sh);
    float e=valid?expf(s-m):0.0f;
    float sum=block_sum(e,sh);
    g_w[b*1024+tid]=valid?(e/sum):0.0f;
}

__global__ void gather_kernel(float* __restrict__ out){
    int t=blockIdx.x*blockDim.x+threadIdx.x;
    if(t>=Bb*KTOP*256) return;
    int c4=t&255, r=t>>8, b=r/KTOP, i=r-b*KTOP;
    int idx=(int)(g_keys[b*Nseq+i]&0xffffffffu);
    size_t src=((size_t)(b*Nseq+idx))*1024+c4*4;
    size_t dst=((size_t)(b*OUTR+i))*1024+c4*4;
    *(float4*)(out+dst)=*(const float4*)(g_hs+src);
    *(float4*)(out+(size_t)Bb*OUTR*1024+dst)=*(const float4*)(g_res+src);
}

__global__ void fused_kernel(float* __restrict__ out){
    int b=blockIdx.x>>3, chunk=blockIdx.x&7;
    int col=chunk*128+threadIdx.x;
    float ah=0.f, ar=0.f;
    for(int i=0;i<REST;i++){
        int idx=(int)(g_keys[b*Nseq+KTOP+i]&0xffffffffu);
        float w=g_w[b*1024+i];
        size_t base=((size_t)(b*Nseq+idx))*1024+col;
        ah=fmaf(w,g_hs[base],ah);
        ar=fmaf(w,g_res[base],ar);
    }
    size_t dst=((size_t)(b*OUTR+KTOP))*1024+col;
    out[dst]=ah;
    out[(size_t)Bb*OUTR*1024+dst]=ar;
}

extern "C" void kernel_launch(void* const* d_in, const int* in_sizes, int n_in,
                              void* d_out, int out_size){
    const float* hidden=(const float*)d_in[0];
    const float* residual=(const float*)d_in[1];
    const float* norm_w=(const float*)d_in[2];
    const float* in_proj_w=(const float*)d_in[3];
    const float* conv_w=(const float*)d_in[4];
    const float* conv_b=(const float*)d_in[5];
    const float* x_proj_w=(const float*)d_in[6];
    const float* dt_proj_w=(const float*)d_in[7];
    const float* dt_proj_b=(const float*)d_in[8];
    const float* A_log=(const float*)d_in[9];
    const float* D_param=(const float*)d_in[10];
    const float* out_proj_w=(const float*)d_in[11];
    float* out=(float*)d_out;

    float *p_xn,*p_xz,*p_xc,*p_xdb,*p_dt,*p_y,*p_hs;
    float *p_nxn,*p_nw1,*p_ny,*p_nw2;
    cudaGetSymbolAddress((void**)&p_xn,g_xn);
    cudaGetSymbolAddress((void**)&p_xz,g_xz);
    cudaGetSymbolAddress((void**)&p_xc,g_xc);
    cudaGetSymbolAddress((void**)&p_xdb,g_xdb);
    cudaGetSymbolAddress((void**)&p_dt,g_dt);
    cudaGetSymbolAddress((void**)&p_y,g_y);
    cudaGetSymbolAddress((void**)&p_hs,g_hs);
    cudaGetSymbolAddress((void**)&p_nxn,g_nxn);
    cudaGetSymbolAddress((void**)&p_nw1,g_nw1);
    cudaGetSymbolAddress((void**)&p_ny,g_ny);
    cudaGetSymbolAddress((void**)&p_nw2,g_nw2);

    add_rmsnorm_kernel<<<Mrows,1024>>>(hidden,residual,norm_w);
    norms_kernel<<<(2*DI)/8,256>>>(in_proj_w,p_nw1,Dd);
    norms_kernel<<<Dd/8,256>>>(out_proj_w,p_nw2,DI);
    norms_kernel<<<Mrows/8,256>>>(p_xn,p_nxn,Dd);
    // in_proj: [4096 x 4096], K=1024  (grid-EFT, KTILE=16, occ=2)
    dgemm_kernel<<<dim3(64,32),256>>>(p_xn,in_proj_w,p_xz,p_nxn,p_nw1,2*DI,Dd,Dd);
    conv_silu_kernel<<<(Mrows*DI)/256,256>>>(conv_w,conv_b);
    // x_proj: [4096 x 96], K=2048  (Kahan)
    kgemm_kernel<0><<<dim3(2,32),256>>>(p_xc,x_proj_w,p_xdb,nullptr,96,DI,DI);
    // dt: softplus([4096 x 2048] @ dtw^T + b), K=64, lda=96  (Kahan)
    kgemm_kernel<1><<<dim3(32,32),256>>>(p_xdb,dt_proj_w,p_dt,dt_proj_b,DI,64,96);
    scan_kernel<<<(Bb*DI)/16,256>>>(A_log,D_param);
    norms_kernel<<<Mrows/8,256>>>(p_y,p_ny,DI);
    // out_proj: [4096 x 1024], K=2048  (grid-EFT)
    dgemm_kernel<<<dim3(16,32),256>>>(p_y,out_proj_w,p_hs,p_ny,p_nw2,Dd,DI,DI);
    scores_kernel<<<Mrows,1024>>>();
    sort_kernel<<<Bb,1024>>>();
    softmax_rest_kernel<<<Bb,1024>>>();
    gather_kernel<<<(Bb*KTOP*256+255)/256,256>>>(out);
    fused_kernel<<<Bb*8,128>>>(out);
}